// round 2
// baseline (speedup 1.0000x reference)
#include <cuda_runtime.h>

// ---------------- problem constants ----------------
#define Bb   2
#define Ss   2048
#define DMm  256
#define DIi  512
#define NN   16
#define RR   32
#define MM   (Bb*Ss)          // 4096 rows
#define CHUNK 32
#define NCH  (Ss/CHUNK)       // 64 chunks per sequence
#define KS   4                // split-K for x-proj

// ---------------- device scratch ----------------
__device__ float g_res [MM*DMm];
__device__ float g_fwd [MM*DMm];
__device__ float g_xn  [MM*DMm];
__device__ float g_xs  [MM*DIi];
__device__ float g_z   [MM*DIi];
__device__ float g_xc  [MM*DIi];
__device__ float g_proj[MM*64];          // [xd(32) | B(16) | C(16)]
__device__ float g_projp[KS*MM*64];      // split-K partials
__device__ float g_delta[MM*DIi];
__device__ float g_yg  [MM*DIi];
__device__ float g_P   [Bb*NCH*DIi*NN];
__device__ float g_Q   [Bb*NCH*DIi*NN];
__device__ float g_Hin [Bb*NCH*DIi*NN];

__device__ __forceinline__ float siluf(float x){ return x / (1.f + __expf(-x)); }
__device__ __forceinline__ float spf(float a){ return (a > 20.f) ? a : log1pf(__expf(a)); }

// packed fp32x2 FMA (FFMA2) — only reachable via PTX
#define FMA2(d,a,b) asm("fma.rn.f32x2 %0, %1, %2, %0;" : "+l"(d) : "l"(a), "l"(b))
__device__ __forceinline__ float LOF(unsigned long long v){ return __uint_as_float((unsigned)v); }
__device__ __forceinline__ float HIF(unsigned long long v){ return __uint_as_float((unsigned)(v>>32)); }

// ---------------- init / copy ----------------
__global__ void k_init(const float* __restrict__ x, int rev){
  int idx = blockIdx.x*256 + threadIdx.x;       // MM*64 float4s
  int col = idx & 63;
  int m   = idx >> 6;
  int b = m >> 11, s = m & (Ss-1);
  int ms = rev ? (b*Ss + (Ss-1-s)) : m;
  reinterpret_cast<float4*>(g_res)[m*64+col] =
      reinterpret_cast<const float4*>(x)[ms*64+col];
}

__global__ void k_copy(){
  int idx = blockIdx.x*256 + threadIdx.x;
  reinterpret_cast<float4*>(g_fwd)[idx] = reinterpret_cast<const float4*>(g_res)[idx];
}

// ---------------- layernorm (1 warp per row of 256) ----------------
__global__ void k_ln(const float* __restrict__ g, const float* __restrict__ bt){
  int warp = (blockIdx.x*256 + threadIdx.x) >> 5;
  int lane = threadIdx.x & 31;
  const float* row = g_res + warp*DMm;
  float4 v0 = reinterpret_cast<const float4*>(row)[lane];
  float4 v1 = reinterpret_cast<const float4*>(row)[lane+32];
  float s = v0.x+v0.y+v0.z+v0.w + v1.x+v1.y+v1.z+v1.w;
  float q = v0.x*v0.x+v0.y*v0.y+v0.z*v0.z+v0.w*v0.w
          + v1.x*v1.x+v1.y*v1.y+v1.z*v1.z+v1.w*v1.w;
  #pragma unroll
  for (int o=16;o;o>>=1){ s += __shfl_xor_sync(~0u,s,o); q += __shfl_xor_sync(~0u,q,o); }
  float mean = s*(1.f/DMm);
  float var  = q*(1.f/DMm) - mean*mean;
  float r = rsqrtf(var + 1e-5f);
  float* orow = g_xn + warp*DMm;
  int c0 = lane*4, c1 = 128 + lane*4;
  float4 o0, o1;
  o0.x=(v0.x-mean)*r*g[c0+0]+bt[c0+0]; o0.y=(v0.y-mean)*r*g[c0+1]+bt[c0+1];
  o0.z=(v0.z-mean)*r*g[c0+2]+bt[c0+2]; o0.w=(v0.w-mean)*r*g[c0+3]+bt[c0+3];
  o1.x=(v1.x-mean)*r*g[c1+0]+bt[c1+0]; o1.y=(v1.y-mean)*r*g[c1+1]+bt[c1+1];
  o1.z=(v1.z-mean)*r*g[c1+2]+bt[c1+2]; o1.w=(v1.w-mean)*r*g[c1+3]+bt[c1+3];
  reinterpret_cast<float4*>(orow)[lane]    = o0;
  reinterpret_cast<float4*>(orow)[lane+32] = o1;
}

// ======================================================================
// SGEMM core: 64x64 tile, 256 threads, 4x4 per thread via FFMA2.
// B is stored DUPLICATED in shared: Bsd[k][2j],[2j+1] = B[k][j].
// ======================================================================
#define G64_DECL()                                                   \
  __shared__ __align__(16) float As[16][64];                         \
  __shared__ __align__(16) float Bsd[16][128];                       \
  const int t = threadIdx.x;                                         \
  const int tx = t & 15, ty = t >> 4;                                \
  const int ar = t >> 2, ak = (t & 3) * 4;                           \
  const int bk = t >> 4, bc = (t & 15) * 4;                          \
  unsigned long long acc[2][4] = {};                                 \
  float4 ra, rb;

#define G64_SMEM()                                                   \
  As[ak+0][ar]=ra.x; As[ak+1][ar]=ra.y;                              \
  As[ak+2][ar]=ra.z; As[ak+3][ar]=ra.w;                              \
  { float4* bp = (float4*)&Bsd[bk][bc*2];                            \
    bp[0] = make_float4(rb.x,rb.x,rb.y,rb.y);                        \
    bp[1] = make_float4(rb.z,rb.z,rb.w,rb.w); }

#define G64_COMP()                                                   \
  _Pragma("unroll")                                                  \
  for (int kk=0; kk<16; kk++){                                       \
    ulonglong2 A0 = *(ulonglong2*)&As[kk][ty*4];                     \
    ulonglong2 B0 = *(ulonglong2*)&Bsd[kk][tx*8];                    \
    ulonglong2 B1 = *(ulonglong2*)&Bsd[kk][tx*8+4];                  \
    FMA2(acc[0][0],A0.x,B0.x); FMA2(acc[0][1],A0.x,B0.y);            \
    FMA2(acc[0][2],A0.x,B1.x); FMA2(acc[0][3],A0.x,B1.y);            \
    FMA2(acc[1][0],A0.y,B0.x); FMA2(acc[1][1],A0.y,B0.y);            \
    FMA2(acc[1][2],A0.y,B1.x); FMA2(acc[1][3],A0.y,B1.y);            \
  }

// in_proj: xn[4096,256] @ in_w[256,1024] -> xs | z
__global__ void k_gemm_in(const float* __restrict__ W){
  int col0 = blockIdx.x*64, row0 = blockIdx.y*64;
  G64_DECL();
  ra = *(const float4*)&g_xn[(row0+ar)*DMm + ak];
  rb = *(const float4*)&W[bk*(2*DIi) + col0 + bc];
  #pragma unroll 1
  for (int k0=0;k0<DMm;k0+=16){
    G64_SMEM();
    __syncthreads();
    if (k0+16 < DMm){
      ra = *(const float4*)&g_xn[(row0+ar)*DMm + k0+16+ak];
      rb = *(const float4*)&W[(k0+16+bk)*(2*DIi) + col0 + bc];
    }
    G64_COMP();
    __syncthreads();
  }
  int c = col0 + tx*4;
  float* dst = (c < DIi) ? g_xs : g_z;
  int cc = (c < DIi) ? c : c - DIi;
  #pragma unroll
  for (int i=0;i<2;i++){
    int r = row0 + ty*4 + 2*i;
    *(float4*)&dst[(size_t)r*DIi + cc] =
        make_float4(LOF(acc[i][0]),LOF(acc[i][1]),LOF(acc[i][2]),LOF(acc[i][3]));
    *(float4*)&dst[(size_t)(r+1)*DIi + cc] =
        make_float4(HIF(acc[i][0]),HIF(acc[i][1]),HIF(acc[i][2]),HIF(acc[i][3]));
  }
}

// x-proj split-K: xc[4096,512] @ [xd|xB|xC][512,64] -> projp[kz]
__global__ void k_gemm_x(const float* __restrict__ xdw,
                         const float* __restrict__ xbw,
                         const float* __restrict__ xcw){
  int kz = blockIdx.x, row0 = blockIdx.y*64;
  int kbase = kz*(DIi/KS);
  G64_DECL();
  const float* src; int ldb, off;
  if      (bc < 32){ src = xdw; ldb = 32; off = bc;      }
  else if (bc < 48){ src = xbw; ldb = 16; off = bc - 32; }
  else             { src = xcw; ldb = 16; off = bc - 48; }
  ra = *(const float4*)&g_xc[(row0+ar)*DIi + kbase + ak];
  rb = *(const float4*)&src[(kbase+bk)*ldb + off];
  #pragma unroll 1
  for (int k0=kbase; k0<kbase+DIi/KS; k0+=16){
    G64_SMEM();
    __syncthreads();
    if (k0+16 < kbase+DIi/KS){
      ra = *(const float4*)&g_xc[(row0+ar)*DIi + k0+16+ak];
      rb = *(const float4*)&src[(k0+16+bk)*ldb + off];
    }
    G64_COMP();
    __syncthreads();
  }
  float* dst = g_projp + (size_t)kz*MM*64;
  int c = tx*4;
  #pragma unroll
  for (int i=0;i<2;i++){
    int r = row0 + ty*4 + 2*i;
    *(float4*)&dst[r*64 + c] =
        make_float4(LOF(acc[i][0]),LOF(acc[i][1]),LOF(acc[i][2]),LOF(acc[i][3]));
    *(float4*)&dst[(r+1)*64 + c] =
        make_float4(HIF(acc[i][0]),HIF(acc[i][1]),HIF(acc[i][2]),HIF(acc[i][3]));
  }
}

__global__ void k_xred(){
  int i = blockIdx.x*256 + threadIdx.x;   // MM*16 float4s
  float4 a = reinterpret_cast<const float4*>(g_projp)[i];
  float4 b = reinterpret_cast<const float4*>(g_projp + MM*64)[i];
  float4 c = reinterpret_cast<const float4*>(g_projp + 2*MM*64)[i];
  float4 d = reinterpret_cast<const float4*>(g_projp + 3*MM*64)[i];
  reinterpret_cast<float4*>(g_proj)[i] =
      make_float4(a.x+b.x+c.x+d.x, a.y+b.y+c.y+d.y,
                  a.z+b.z+c.z+d.z, a.w+b.w+c.w+d.w);
}

// delta: softplus(proj[:, :32] @ dtp_w[32,512] + dtp_b)
__global__ void k_gemm_dt(const float* __restrict__ Wd, const float* __restrict__ bd){
  int col0 = blockIdx.x*64, row0 = blockIdx.y*64;
  G64_DECL();
  ra = *(const float4*)&g_proj[(row0+ar)*64 + ak];
  rb = *(const float4*)&Wd[bk*DIi + col0 + bc];
  #pragma unroll 1
  for (int k0=0;k0<RR;k0+=16){
    G64_SMEM();
    __syncthreads();
    if (k0+16 < RR){
      ra = *(const float4*)&g_proj[(row0+ar)*64 + k0+16+ak];
      rb = *(const float4*)&Wd[(k0+16+bk)*DIi + col0 + bc];
    }
    G64_COMP();
    __syncthreads();
  }
  int c = col0 + tx*4;
  float4 bv = *(const float4*)&bd[c];
  #pragma unroll
  for (int i=0;i<2;i++){
    int r = row0 + ty*4 + 2*i;
    *(float4*)&g_delta[(size_t)r*DIi + c] =
        make_float4(spf(LOF(acc[i][0])+bv.x), spf(LOF(acc[i][1])+bv.y),
                    spf(LOF(acc[i][2])+bv.z), spf(LOF(acc[i][3])+bv.w));
    *(float4*)&g_delta[(size_t)(r+1)*DIi + c] =
        make_float4(spf(HIF(acc[i][0])+bv.x), spf(HIF(acc[i][1])+bv.y),
                    spf(HIF(acc[i][2])+bv.z), spf(HIF(acc[i][3])+bv.w));
  }
}

// out_proj: yg[4096,512] @ out_w[512,256] + residual
__global__ void k_gemm_out(const float* __restrict__ W){
  int col0 = blockIdx.x*64, row0 = blockIdx.y*64;
  G64_DECL();
  ra = *(const float4*)&g_yg[(row0+ar)*DIi + ak];
  rb = *(const float4*)&W[bk*DMm + col0 + bc];
  #pragma unroll 1
  for (int k0=0;k0<DIi;k0+=16){
    G64_SMEM();
    __syncthreads();
    if (k0+16 < DIi){
      ra = *(const float4*)&g_yg[(row0+ar)*DIi + k0+16+ak];
      rb = *(const float4*)&W[(k0+16+bk)*DMm + col0 + bc];
    }
    G64_COMP();
    __syncthreads();
  }
  int c = col0 + tx*4;
  #pragma unroll
  for (int i=0;i<2;i++){
    int r = row0 + ty*4 + 2*i;
    float4 o0 = *(const float4*)&g_res[r*DMm + c];
    float4 o1 = *(const float4*)&g_res[(r+1)*DMm + c];
    *(float4*)&g_res[r*DMm + c] =
        make_float4(LOF(acc[i][0])+o0.x, LOF(acc[i][1])+o0.y,
                    LOF(acc[i][2])+o0.z, LOF(acc[i][3])+o0.w);
    *(float4*)&g_res[(r+1)*DMm + c] =
        make_float4(HIF(acc[i][0])+o1.x, HIF(acc[i][1])+o1.y,
                    HIF(acc[i][2])+o1.z, HIF(acc[i][3])+o1.w);
  }
}

// merge: concat(fwd, res_reversed)[4096,512] @ merge_w[512,256] -> out
__global__ void k_merge(const float* __restrict__ W, float* __restrict__ out){
  int col0 = blockIdx.x*64, row0 = blockIdx.y*64;
  G64_DECL();
  int r = row0 + ar;
  int b = r >> 11, s = r & (Ss-1);
  int rrev = b*Ss + (Ss-1-s);
  {
    int kk = ak;
    const float* pa = (kk < DMm) ? (g_fwd + r*DMm + kk) : (g_res + rrev*DMm + kk - DMm);
    ra = *(const float4*)pa;
    rb = *(const float4*)&W[bk*DMm + col0 + bc];
  }
  #pragma unroll 1
  for (int k0=0;k0<2*DMm;k0+=16){
    G64_SMEM();
    __syncthreads();
    if (k0+16 < 2*DMm){
      int kk = k0+16+ak;
      const float* pa = (kk < DMm) ? (g_fwd + r*DMm + kk) : (g_res + rrev*DMm + kk - DMm);
      ra = *(const float4*)pa;
      rb = *(const float4*)&W[(k0+16+bk)*DMm + col0 + bc];
    }
    G64_COMP();
    __syncthreads();
  }
  int c = col0 + tx*4;
  #pragma unroll
  for (int i=0;i<2;i++){
    int rr = row0 + ty*4 + 2*i;
    *(float4*)&out[rr*DMm + c] =
        make_float4(LOF(acc[i][0]),LOF(acc[i][1]),LOF(acc[i][2]),LOF(acc[i][3]));
    *(float4*)&out[(rr+1)*DMm + c] =
        make_float4(HIF(acc[i][0]),HIF(acc[i][1]),HIF(acc[i][2]),HIF(acc[i][3]));
  }
}

// ---------------- causal depthwise conv (K=4) + silu, 8 s-positions/thread ----------------
__global__ void k_conv(const float* __restrict__ cw, const float* __restrict__ cb){
  int idx = blockIdx.x*256 + threadIdx.x;   // (MM/8)*128
  int d4 = idx & 127, g = idx >> 7;         // g in [0, MM/8)
  int b = g >> 8, sg = g & 255;
  int m0 = b*Ss + sg*8;
  int d = d4*4;
  float4 w0 = *(const float4*)(cw + (d+0)*4);
  float4 w1 = *(const float4*)(cw + (d+1)*4);
  float4 w2 = *(const float4*)(cw + (d+2)*4);
  float4 w3 = *(const float4*)(cw + (d+3)*4);
  float4 bv = *(const float4*)(cb + d);
  float4 x0, x1, x2;
  if (sg > 0){
    x0 = *(const float4*)&g_xs[(m0-3)*DIi + d];
    x1 = *(const float4*)&g_xs[(m0-2)*DIi + d];
    x2 = *(const float4*)&g_xs[(m0-1)*DIi + d];
  } else {
    x0 = x1 = x2 = make_float4(0.f,0.f,0.f,0.f);
  }
  #pragma unroll
  for (int s=0;s<8;s++){
    float4 x3 = *(const float4*)&g_xs[(m0+s)*DIi + d];
    float4 a;
    a.x = bv.x + w0.x*x0.x + w0.y*x1.x + w0.z*x2.x + w0.w*x3.x;
    a.y = bv.y + w1.x*x0.y + w1.y*x1.y + w1.z*x2.y + w1.w*x3.y;
    a.z = bv.z + w2.x*x0.z + w2.y*x1.z + w2.z*x2.z + w2.w*x3.z;
    a.w = bv.w + w3.x*x0.w + w3.y*x1.w + w3.z*x2.w + w3.w*x3.w;
    a.x = siluf(a.x); a.y = siluf(a.y); a.z = siluf(a.z); a.w = siluf(a.w);
    *(float4*)&g_xc[(m0+s)*DIi + d] = a;
    x0 = x1; x1 = x2; x2 = x3;
  }
}

// ---------------- chunked scan phase 1 ----------------
__global__ void k_scan1(const float* __restrict__ Alog){
  __shared__ float sB[CHUNK][NN];
  int bc_ = blockIdx.x;
  int b = bc_ >> 6, c = bc_ & 63;
  int d = threadIdx.x;
  int m0 = b*Ss + c*CHUNK;
  { int s = d >> 4, n = d & 15; sB[s][n] = g_proj[(m0+s)*64 + 32 + n]; }
  float A[NN];
  #pragma unroll
  for (int n=0;n<NN;n++) A[n] = -__expf(Alog[d*NN + n]);
  __syncthreads();
  float h[NN];
  #pragma unroll
  for (int n=0;n<NN;n++) h[n] = 0.f;
  float sd = 0.f;
  #pragma unroll 1
  for (int s=0;s<CHUNK;s++){
    int m = m0 + s;
    float dlt = g_delta[m*DIi + d];
    float dx  = dlt * g_xc[m*DIi + d];
    sd += dlt;
    #pragma unroll
    for (int n=0;n<NN;n++){
      float dA = __expf(dlt*A[n]);
      h[n] = dA*h[n] + dx*sB[s][n];
    }
  }
  int base = (bc_*DIi + d)*NN;
  #pragma unroll
  for (int n=0;n<NN;n++){ g_Q[base+n]=h[n]; g_P[base+n]=__expf(sd*A[n]); }
}

// ---------------- phase 2: combine across chunks ----------------
__global__ void k_comb(){
  int i = blockIdx.x*256 + threadIdx.x;     // Bb*DIi*NN = 16384
  int n = i & 15, d = (i >> 4) & (DIi-1), b = i >> 13;
  float H = 0.f;
  #pragma unroll 1
  for (int c=0;c<NCH;c++){
    int idx = ((b*NCH+c)*DIi + d)*NN + n;
    g_Hin[idx] = H;
    H = g_P[idx]*H + g_Q[idx];
  }
}

// ---------------- phase 3: replay + gated output ----------------
__global__ void k_scan2(const float* __restrict__ Alog, const float* __restrict__ Dp){
  __shared__ float sB[CHUNK][NN];
  __shared__ float sC[CHUNK][NN];
  int bc_ = blockIdx.x;
  int b = bc_ >> 6, c = bc_ & 63;
  int d = threadIdx.x;
  int m0 = b*Ss + c*CHUNK;
  { int s = d >> 4, n = d & 15;
    sB[s][n] = g_proj[(m0+s)*64 + 32 + n];
    sC[s][n] = g_proj[(m0+s)*64 + 48 + n]; }
  float A[NN];
  #pragma unroll
  for (int n=0;n<NN;n++) A[n] = -__expf(Alog[d*NN + n]);
  float h[NN];
  int base = (bc_*DIi + d)*NN;
  #pragma unroll
  for (int n=0;n<NN;n++) h[n] = g_Hin[base+n];
  float Dv = Dp[d];
  __syncthreads();
  #pragma unroll 1
  for (int s=0;s<CHUNK;s++){
    int m = m0 + s;
    float dlt = g_delta[m*DIi + d];
    float x   = g_xc[m*DIi + d];
    float dx  = dlt * x;
    float y = 0.f;
    #pragma unroll
    for (int n=0;n<NN;n++){
      float dA = __expf(dlt*A[n]);
      h[n] = dA*h[n] + dx*sB[s][n];
      y += h[n]*sC[s][n];
    }
    y += Dv*x;
    float zv = g_z[m*DIi + d];
    g_yg[m*DIi + d] = y * siluf(zv);
  }
}

// ---------------- driver ----------------
extern "C" void kernel_launch(void* const* d_in, const int* in_sizes, int n_in,
                              void* d_out, int out_size){
  const float* x      = (const float*)d_in[0];
  const float* in_w   = (const float*)d_in[1];
  const float* conv_w = (const float*)d_in[2];
  const float* conv_b = (const float*)d_in[3];
  const float* A_log  = (const float*)d_in[4];
  const float* xd_w   = (const float*)d_in[5];
  const float* xB_w   = (const float*)d_in[6];
  const float* xC_w   = (const float*)d_in[7];
  const float* dtp_w  = (const float*)d_in[8];
  const float* dtp_b  = (const float*)d_in[9];
  const float* Dp     = (const float*)d_in[10];
  const float* out_w  = (const float*)d_in[11];
  const float* ln_g   = (const float*)d_in[12];
  const float* ln_b   = (const float*)d_in[13];
  const float* merge_w= (const float*)d_in[14];
  float* out = (float*)d_out;

  for (int chain=0; chain<2; chain++){
    k_init<<<MM*64/256, 256>>>(x, chain);
    for (int bi=0; bi<2; bi++){
      int blk = chain*2 + bi;
      k_ln      <<<MM/8, 256>>>(ln_g + blk*DMm, ln_b + blk*DMm);
      k_gemm_in <<<dim3(16,64), 256>>>(in_w + (size_t)blk*DMm*2*DIi);
      k_conv    <<<(MM/8)*128/256, 256>>>(conv_w + blk*DIi*4, conv_b + blk*DIi);
      k_gemm_x  <<<dim3(KS,64), 256>>>(xd_w + blk*DIi*RR,
                                       xB_w + blk*DIi*NN,
                                       xC_w + blk*DIi*NN);
      k_xred    <<<MM*16/256, 256>>>();
      k_gemm_dt <<<dim3(8,64), 256>>>(dtp_w + blk*RR*DIi, dtp_b + blk*DIi);
      k_scan1   <<<Bb*NCH, DIi>>>(A_log + blk*DIi*NN);
      k_comb    <<<64, 256>>>();
      k_scan2   <<<Bb*NCH, DIi>>>(A_log + blk*DIi*NN, Dp + blk*DIi);
      k_gemm_out<<<dim3(4,64), 256>>>(out_w + blk*DIi*DMm);
    }
    if (chain == 0) k_copy<<<MM*64/256, 256>>>();
  }
  k_merge<<<dim3(4,64), 256>>>(merge_w, out);
}

// round 3
// speedup vs baseline: 2.1036x; 2.1036x over previous
#include <cuda_runtime.h>

// ---------------- problem constants ----------------
#define Bb   2
#define Ss   2048
#define DMm  256
#define DIi  512
#define NN   16
#define RR   32
#define MM   (Bb*Ss)          // 4096 rows
#define CHUNK 32
#define NCH  (Ss/CHUNK)       // 64 chunks per sequence
#define KS   4                // split-K for x-proj

// ---------------- device scratch ----------------
__device__ float g_res [MM*DMm];
__device__ float g_fwd [MM*DMm];
__device__ float g_xn  [MM*DMm];
__device__ float g_xs  [MM*DIi];
__device__ float g_z   [MM*DIi];
__device__ float g_xc  [MM*DIi];
__device__ float g_proj[MM*64];          // [xd(32) | B(16) | C(16)]
__device__ float g_projp[KS*MM*64];      // split-K partials
__device__ float g_delta[MM*DIi];
__device__ float g_yg  [MM*DIi];
__device__ float g_P   [Bb*NCH*DIi*NN];
__device__ float g_Q   [Bb*NCH*DIi*NN];
__device__ float g_Hin [Bb*NCH*DIi*NN];

__device__ __forceinline__ float siluf(float x){ return x / (1.f + __expf(-x)); }
__device__ __forceinline__ float spf(float a){ return (a > 20.f) ? a : log1pf(__expf(a)); }

__device__ __forceinline__ unsigned tf32c(float f){
  unsigned r; asm("cvt.rna.tf32.f32 %0, %1;" : "=r"(r) : "f"(f)); return r;
}

#define MMA8(c, a, b)                                                        \
  asm volatile("mma.sync.aligned.m16n8k8.row.col.f32.tf32.tf32.f32 "         \
               "{%0,%1,%2,%3},{%4,%5,%6,%7},{%8,%9},{%0,%1,%2,%3};"          \
               : "+f"(c[0]), "+f"(c[1]), "+f"(c[2]), "+f"(c[3])              \
               : "r"(a[0]), "r"(a[1]), "r"(a[2]), "r"(a[3]),                 \
                 "r"(b[0]), "r"(b[1]))

// ---------------- init / copy ----------------
__global__ void k_init(const float* __restrict__ x, int rev){
  int idx = blockIdx.x*256 + threadIdx.x;       // MM*64 float4s
  int col = idx & 63;
  int m   = idx >> 6;
  int b = m >> 11, s = m & (Ss-1);
  int ms = rev ? (b*Ss + (Ss-1-s)) : m;
  reinterpret_cast<float4*>(g_res)[m*64+col] =
      reinterpret_cast<const float4*>(x)[ms*64+col];
}

__global__ void k_copy(){
  int idx = blockIdx.x*256 + threadIdx.x;
  reinterpret_cast<float4*>(g_fwd)[idx] = reinterpret_cast<const float4*>(g_res)[idx];
}

// ---------------- layernorm (1 warp per row of 256) ----------------
__global__ void k_ln(const float* __restrict__ g, const float* __restrict__ bt){
  int warp = (blockIdx.x*256 + threadIdx.x) >> 5;
  int lane = threadIdx.x & 31;
  const float* row = g_res + warp*DMm;
  float4 v0 = reinterpret_cast<const float4*>(row)[lane];
  float4 v1 = reinterpret_cast<const float4*>(row)[lane+32];
  float s = v0.x+v0.y+v0.z+v0.w + v1.x+v1.y+v1.z+v1.w;
  float q = v0.x*v0.x+v0.y*v0.y+v0.z*v0.z+v0.w*v0.w
          + v1.x*v1.x+v1.y*v1.y+v1.z*v1.z+v1.w*v1.w;
  #pragma unroll
  for (int o=16;o;o>>=1){ s += __shfl_xor_sync(~0u,s,o); q += __shfl_xor_sync(~0u,q,o); }
  float mean = s*(1.f/DMm);
  float var  = q*(1.f/DMm) - mean*mean;
  float r = rsqrtf(var + 1e-5f);
  float* orow = g_xn + warp*DMm;
  int c0 = lane*4, c1 = 128 + lane*4;
  float4 o0, o1;
  o0.x=(v0.x-mean)*r*g[c0+0]+bt[c0+0]; o0.y=(v0.y-mean)*r*g[c0+1]+bt[c0+1];
  o0.z=(v0.z-mean)*r*g[c0+2]+bt[c0+2]; o0.w=(v0.w-mean)*r*g[c0+3]+bt[c0+3];
  o1.x=(v1.x-mean)*r*g[c1+0]+bt[c1+0]; o1.y=(v1.y-mean)*r*g[c1+1]+bt[c1+1];
  o1.z=(v1.z-mean)*r*g[c1+2]+bt[c1+2]; o1.w=(v1.w-mean)*r*g[c1+3]+bt[c1+3];
  reinterpret_cast<float4*>(orow)[lane]    = o0;
  reinterpret_cast<float4*>(orow)[lane+32] = o1;
}

// ======================================================================
// TF32 tensor-core GEMM core.
// Block tile 128(M) x 64(N), 256 threads = 8 warps (4 M x 2 N).
// Warp tile 32x32 = 2 m-tiles(16) x 4 n-tiles(8), mma.m16n8k8, K-chunk 16.
// Smem holds operands PRE-PERMUTED into mma fragment order:
//   Af[mt(8)][k8(2)][reg(4)][lane(32)]  (tf32)
//   Bf[nt(8)][k8(2)][reg(2)][lane(32)]  (tf32)
// so compute-side loads are conflict-free coalesced LDS.32.
// ======================================================================
#define TC_DECL()                                                     \
  __shared__ __align__(16) unsigned Af[2048];                         \
  __shared__ __align__(16) unsigned Bf[1024];                         \
  const int t = threadIdx.x;                                          \
  const int lane = t & 31, wid = t >> 5;                              \
  const int wm = wid >> 1, wn = wid & 1;                              \
  const int s_r  = t >> 1;          /* A staging row 0..127  */       \
  const int s_kb = (t & 1) * 8;     /* A staging k base 0/8  */       \
  const int s_bk = t >> 4;          /* B staging k 0..15     */       \
  const int s_bn = (t & 15) * 4;    /* B staging n 0..60     */       \
  float acc[2][4][4] = {};                                            \
  float4 raA0, raA1, raB;

#define TC_STAGE() {                                                  \
  int mt_ = s_r >> 4, rr_ = s_r & 15;                                 \
  int lane0_ = (rr_ & 7) * 4;                                         \
  int regb_ = (rr_ >= 8) ? 1 : 0;                                     \
  { int kk = s_kb;   int k8 = kk >> 3; int rg = regb_ + ((kk & 4) ? 2 : 0); \
    uint4 v = make_uint4(tf32c(raA0.x),tf32c(raA0.y),tf32c(raA0.z),tf32c(raA0.w)); \
    *(uint4*)&Af[(((mt_*2 + k8)*4 + rg)*32) + lane0_] = v; }          \
  { int kk = s_kb+4; int k8 = kk >> 3; int rg = regb_ + ((kk & 4) ? 2 : 0); \
    uint4 v = make_uint4(tf32c(raA1.x),tf32c(raA1.y),tf32c(raA1.z),tf32c(raA1.w)); \
    *(uint4*)&Af[(((mt_*2 + k8)*4 + rg)*32) + lane0_] = v; }          \
  { int k8 = s_bk >> 3, rg = (s_bk & 4) ? 1 : 0, kc3 = s_bk & 3;      \
    float bv_[4] = {raB.x, raB.y, raB.z, raB.w};                      \
    _Pragma("unroll") for (int i_=0;i_<4;i_++){                       \
      int n_ = s_bn + i_, nt_ = n_ >> 3, c_ = n_ & 7;                 \
      Bf[(((nt_*2 + k8)*2 + rg)*32) + c_*4 + kc3] = tf32c(bv_[i_]); } } }

#define TC_COMP()                                                     \
  _Pragma("unroll")                                                   \
  for (int k8=0;k8<2;k8++){                                           \
    unsigned a_[2][4], b_[4][2];                                      \
    _Pragma("unroll") for (int mt=0;mt<2;mt++){                       \
      int ba = (((wm*2+mt)*2 + k8)*4)*32 + lane;                      \
      a_[mt][0]=Af[ba]; a_[mt][1]=Af[ba+32];                          \
      a_[mt][2]=Af[ba+64]; a_[mt][3]=Af[ba+96]; }                     \
    _Pragma("unroll") for (int nt=0;nt<4;nt++){                       \
      int bb = (((wn*4+nt)*2 + k8)*2)*32 + lane;                      \
      b_[nt][0]=Bf[bb]; b_[nt][1]=Bf[bb+32]; }                        \
    _Pragma("unroll") for (int mt=0;mt<2;mt++)                        \
      _Pragma("unroll") for (int nt=0;nt<4;nt++)                      \
        MMA8(acc[mt][nt], a_[mt], b_[nt]);                            \
  }

// in_proj: xn[4096,256] @ in_w[256,1024] -> xs | z
__global__ void k_gemm_in(const float* __restrict__ W){
  int col0 = blockIdx.x*64, row0 = blockIdx.y*128;
  TC_DECL();
  raA0 = *(const float4*)&g_xn[(row0+s_r)*DMm + s_kb];
  raA1 = *(const float4*)&g_xn[(row0+s_r)*DMm + s_kb+4];
  raB  = *(const float4*)&W[s_bk*(2*DIi) + col0 + s_bn];
  #pragma unroll 1
  for (int k0=0;k0<DMm;k0+=16){
    TC_STAGE();
    __syncthreads();
    if (k0+16 < DMm){
      raA0 = *(const float4*)&g_xn[(row0+s_r)*DMm + k0+16+s_kb];
      raA1 = *(const float4*)&g_xn[(row0+s_r)*DMm + k0+16+s_kb+4];
      raB  = *(const float4*)&W[(k0+16+s_bk)*(2*DIi) + col0 + s_bn];
    }
    TC_COMP();
    __syncthreads();
  }
  float* dst = (col0 < DIi) ? g_xs : g_z;
  int cb = (col0 < DIi) ? col0 : col0 - DIi;
  #pragma unroll
  for (int mt=0;mt<2;mt++)
    #pragma unroll
    for (int nt=0;nt<4;nt++){
      int r = row0 + wm*32 + mt*16 + (lane>>2);
      int c = cb + wn*32 + nt*8 + (lane&3)*2;
      *(float2*)&dst[(size_t)r*DIi + c]     = make_float2(acc[mt][nt][0], acc[mt][nt][1]);
      *(float2*)&dst[(size_t)(r+8)*DIi + c] = make_float2(acc[mt][nt][2], acc[mt][nt][3]);
    }
}

// x-proj split-K: xc[4096,512] @ [xd(32)|xB(16)|xC(16)] -> projp[kz]
__global__ void k_gemm_x(const float* __restrict__ xdw,
                         const float* __restrict__ xbw,
                         const float* __restrict__ xcw){
  int kz = blockIdx.x, row0 = blockIdx.y*128;
  int kbase = kz*(DIi/KS);
  TC_DECL();
  const float* bsrc; int ldb, boff;
  if      (s_bn < 32){ bsrc = xdw; ldb = 32; boff = s_bn;      }
  else if (s_bn < 48){ bsrc = xbw; ldb = 16; boff = s_bn - 32; }
  else               { bsrc = xcw; ldb = 16; boff = s_bn - 48; }
  raA0 = *(const float4*)&g_xc[(row0+s_r)*DIi + kbase + s_kb];
  raA1 = *(const float4*)&g_xc[(row0+s_r)*DIi + kbase + s_kb+4];
  raB  = *(const float4*)&bsrc[(kbase+s_bk)*ldb + boff];
  #pragma unroll 1
  for (int k0=kbase; k0<kbase+DIi/KS; k0+=16){
    TC_STAGE();
    __syncthreads();
    if (k0+16 < kbase+DIi/KS){
      raA0 = *(const float4*)&g_xc[(row0+s_r)*DIi + k0+16+s_kb];
      raA1 = *(const float4*)&g_xc[(row0+s_r)*DIi + k0+16+s_kb+4];
      raB  = *(const float4*)&bsrc[(k0+16+s_bk)*ldb + boff];
    }
    TC_COMP();
    __syncthreads();
  }
  float* dst = g_projp + (size_t)kz*MM*64;
  #pragma unroll
  for (int mt=0;mt<2;mt++)
    #pragma unroll
    for (int nt=0;nt<4;nt++){
      int r = row0 + wm*32 + mt*16 + (lane>>2);
      int c = wn*32 + nt*8 + (lane&3)*2;
      *(float2*)&dst[r*64 + c]     = make_float2(acc[mt][nt][0], acc[mt][nt][1]);
      *(float2*)&dst[(r+8)*64 + c] = make_float2(acc[mt][nt][2], acc[mt][nt][3]);
    }
}

__global__ void k_xred(){
  int i = blockIdx.x*256 + threadIdx.x;   // MM*16 float4s
  float4 a = reinterpret_cast<const float4*>(g_projp)[i];
  float4 b = reinterpret_cast<const float4*>(g_projp + MM*64)[i];
  float4 c = reinterpret_cast<const float4*>(g_projp + 2*MM*64)[i];
  float4 d = reinterpret_cast<const float4*>(g_projp + 3*MM*64)[i];
  reinterpret_cast<float4*>(g_proj)[i] =
      make_float4(a.x+b.x+c.x+d.x, a.y+b.y+c.y+d.y,
                  a.z+b.z+c.z+d.z, a.w+b.w+c.w+d.w);
}

// delta: softplus(proj[:, :32] @ dtp_w[32,512] + dtp_b) -> g_delta
__global__ void k_gemm_dt(const float* __restrict__ Wd, const float* __restrict__ bd){
  int col0 = blockIdx.x*64, row0 = blockIdx.y*128;
  TC_DECL();
  raA0 = *(const float4*)&g_proj[(row0+s_r)*64 + s_kb];
  raA1 = *(const float4*)&g_proj[(row0+s_r)*64 + s_kb+4];
  raB  = *(const float4*)&Wd[s_bk*DIi + col0 + s_bn];
  #pragma unroll 1
  for (int k0=0;k0<RR;k0+=16){
    TC_STAGE();
    __syncthreads();
    if (k0+16 < RR){
      raA0 = *(const float4*)&g_proj[(row0+s_r)*64 + k0+16+s_kb];
      raA1 = *(const float4*)&g_proj[(row0+s_r)*64 + k0+16+s_kb+4];
      raB  = *(const float4*)&Wd[(k0+16+s_bk)*DIi + col0 + s_bn];
    }
    TC_COMP();
    __syncthreads();
  }
  #pragma unroll
  for (int mt=0;mt<2;mt++)
    #pragma unroll
    for (int nt=0;nt<4;nt++){
      int r = row0 + wm*32 + mt*16 + (lane>>2);
      int c = col0 + wn*32 + nt*8 + (lane&3)*2;
      float b0 = bd[c], b1 = bd[c+1];
      *(float2*)&g_delta[(size_t)r*DIi + c] =
          make_float2(spf(acc[mt][nt][0]+b0), spf(acc[mt][nt][1]+b1));
      *(float2*)&g_delta[(size_t)(r+8)*DIi + c] =
          make_float2(spf(acc[mt][nt][2]+b0), spf(acc[mt][nt][3]+b1));
    }
}

// out_proj: yg[4096,512] @ out_w[512,256] + residual (in place on g_res)
__global__ void k_gemm_out(const float* __restrict__ W){
  int col0 = blockIdx.x*64, row0 = blockIdx.y*128;
  TC_DECL();
  raA0 = *(const float4*)&g_yg[(row0+s_r)*DIi + s_kb];
  raA1 = *(const float4*)&g_yg[(row0+s_r)*DIi + s_kb+4];
  raB  = *(const float4*)&W[s_bk*DMm + col0 + s_bn];
  #pragma unroll 1
  for (int k0=0;k0<DIi;k0+=16){
    TC_STAGE();
    __syncthreads();
    if (k0+16 < DIi){
      raA0 = *(const float4*)&g_yg[(row0+s_r)*DIi + k0+16+s_kb];
      raA1 = *(const float4*)&g_yg[(row0+s_r)*DIi + k0+16+s_kb+4];
      raB  = *(const float4*)&W[(k0+16+s_bk)*DMm + col0 + s_bn];
    }
    TC_COMP();
    __syncthreads();
  }
  #pragma unroll
  for (int mt=0;mt<2;mt++)
    #pragma unroll
    for (int nt=0;nt<4;nt++){
      int r = row0 + wm*32 + mt*16 + (lane>>2);
      int c = col0 + wn*32 + nt*8 + (lane&3)*2;
      float2 o0 = *(const float2*)&g_res[(size_t)r*DMm + c];
      float2 o1 = *(const float2*)&g_res[(size_t)(r+8)*DMm + c];
      *(float2*)&g_res[(size_t)r*DMm + c] =
          make_float2(acc[mt][nt][0]+o0.x, acc[mt][nt][1]+o0.y);
      *(float2*)&g_res[(size_t)(r+8)*DMm + c] =
          make_float2(acc[mt][nt][2]+o1.x, acc[mt][nt][3]+o1.y);
    }
}

// merge: concat(fwd, res_reversed)[4096,512] @ merge_w[512,256] -> out
__global__ void k_merge(const float* __restrict__ W, float* __restrict__ out){
  int col0 = blockIdx.x*64, row0 = blockIdx.y*128;
  TC_DECL();
  int r_ = row0 + s_r;
  int b_ = r_ >> 11, s_ = r_ & (Ss-1);
  int rrev = b_*Ss + (Ss-1-s_);
  {
    int kk0 = s_kb, kk1 = s_kb+4;
    raA0 = *(const float4*)((kk0 < DMm) ? (g_fwd + r_*DMm + kk0) : (g_res + rrev*DMm + kk0-DMm));
    raA1 = *(const float4*)((kk1 < DMm) ? (g_fwd + r_*DMm + kk1) : (g_res + rrev*DMm + kk1-DMm));
    raB  = *(const float4*)&W[s_bk*DMm + col0 + s_bn];
  }
  #pragma unroll 1
  for (int k0=0;k0<2*DMm;k0+=16){
    TC_STAGE();
    __syncthreads();
    if (k0+16 < 2*DMm){
      int kk0 = k0+16+s_kb, kk1 = k0+16+s_kb+4;
      raA0 = *(const float4*)((kk0 < DMm) ? (g_fwd + r_*DMm + kk0) : (g_res + rrev*DMm + kk0-DMm));
      raA1 = *(const float4*)((kk1 < DMm) ? (g_fwd + r_*DMm + kk1) : (g_res + rrev*DMm + kk1-DMm));
      raB  = *(const float4*)&W[(k0+16+s_bk)*DMm + col0 + s_bn];
    }
    TC_COMP();
    __syncthreads();
  }
  #pragma unroll
  for (int mt=0;mt<2;mt++)
    #pragma unroll
    for (int nt=0;nt<4;nt++){
      int r = row0 + wm*32 + mt*16 + (lane>>2);
      int c = col0 + wn*32 + nt*8 + (lane&3)*2;
      *(float2*)&out[(size_t)r*DMm + c]     = make_float2(acc[mt][nt][0], acc[mt][nt][1]);
      *(float2*)&out[(size_t)(r+8)*DMm + c] = make_float2(acc[mt][nt][2], acc[mt][nt][3]);
    }
}

// ---------------- causal depthwise conv (K=4) + silu, 8 s-positions/thread ----------------
__global__ void k_conv(const float* __restrict__ cw, const float* __restrict__ cb){
  int idx = blockIdx.x*256 + threadIdx.x;   // (MM/8)*128
  int d4 = idx & 127, g = idx >> 7;         // g in [0, MM/8)
  int b = g >> 8, sg = g & 255;
  int m0 = b*Ss + sg*8;
  int d = d4*4;
  float4 w0 = *(const float4*)(cw + (d+0)*4);
  float4 w1 = *(const float4*)(cw + (d+1)*4);
  float4 w2 = *(const float4*)(cw + (d+2)*4);
  float4 w3 = *(const float4*)(cw + (d+3)*4);
  float4 bv = *(const float4*)(cb + d);
  float4 x0, x1, x2;
  if (sg > 0){
    x0 = *(const float4*)&g_xs[(m0-3)*DIi + d];
    x1 = *(const float4*)&g_xs[(m0-2)*DIi + d];
    x2 = *(const float4*)&g_xs[(m0-1)*DIi + d];
  } else {
    x0 = x1 = x2 = make_float4(0.f,0.f,0.f,0.f);
  }
  #pragma unroll
  for (int s=0;s<8;s++){
    float4 x3 = *(const float4*)&g_xs[(m0+s)*DIi + d];
    float4 a;
    a.x = bv.x + w0.x*x0.x + w0.y*x1.x + w0.z*x2.x + w0.w*x3.x;
    a.y = bv.y + w1.x*x0.y + w1.y*x1.y + w1.z*x2.y + w1.w*x3.y;
    a.z = bv.z + w2.x*x0.z + w2.y*x1.z + w2.z*x2.z + w2.w*x3.z;
    a.w = bv.w + w3.x*x0.w + w3.y*x1.w + w3.z*x2.w + w3.w*x3.w;
    a.x = siluf(a.x); a.y = siluf(a.y); a.z = siluf(a.z); a.w = siluf(a.w);
    *(float4*)&g_xc[(m0+s)*DIi + d] = a;
    x0 = x1; x1 = x2; x2 = x3;
  }
}

// ---------------- chunked scan phase 1 ----------------
__global__ void k_scan1(const float* __restrict__ Alog){
  __shared__ float sB[CHUNK][NN];
  int bc_ = blockIdx.x;
  int b = bc_ >> 6, c = bc_ & 63;
  int d = threadIdx.x;
  int m0 = b*Ss + c*CHUNK;
  { int s = d >> 4, n = d & 15; sB[s][n] = g_proj[(m0+s)*64 + 32 + n]; }
  float A[NN];
  #pragma unroll
  for (int n=0;n<NN;n++) A[n] = -__expf(Alog[d*NN + n]);
  __syncthreads();
  float h[NN];
  #pragma unroll
  for (int n=0;n<NN;n++) h[n] = 0.f;
  float sd = 0.f;
  #pragma unroll 1
  for (int s=0;s<CHUNK;s++){
    int m = m0 + s;
    float dlt = g_delta[m*DIi + d];
    float dx  = dlt * g_xc[m*DIi + d];
    sd += dlt;
    #pragma unroll
    for (int n=0;n<NN;n++){
      float dA = __expf(dlt*A[n]);
      h[n] = dA*h[n] + dx*sB[s][n];
    }
  }
  int base = (bc_*DIi + d)*NN;
  #pragma unroll
  for (int n=0;n<NN;n++){ g_Q[base+n]=h[n]; g_P[base+n]=__expf(sd*A[n]); }
}

// ---------------- phase 2: combine across chunks ----------------
__global__ void k_comb(){
  int i = blockIdx.x*256 + threadIdx.x;     // Bb*DIi*NN = 16384
  int n = i & 15, d = (i >> 4) & (DIi-1), b = i >> 13;
  float H = 0.f;
  #pragma unroll 1
  for (int c=0;c<NCH;c++){
    int idx = ((b*NCH+c)*DIi + d)*NN + n;
    g_Hin[idx] = H;
    H = g_P[idx]*H + g_Q[idx];
  }
}

// ---------------- phase 3: replay + gated output ----------------
__global__ void k_scan2(const float* __restrict__ Alog, const float* __restrict__ Dp){
  __shared__ float sB[CHUNK][NN];
  __shared__ float sC[CHUNK][NN];
  int bc_ = blockIdx.x;
  int b = bc_ >> 6, c = bc_ & 63;
  int d = threadIdx.x;
  int m0 = b*Ss + c*CHUNK;
  { int s = d >> 4, n = d & 15;
    sB[s][n] = g_proj[(m0+s)*64 + 32 + n];
    sC[s][n] = g_proj[(m0+s)*64 + 48 + n]; }
  float A[NN];
  #pragma unroll
  for (int n=0;n<NN;n++) A[n] = -__expf(Alog[d*NN + n]);
  float h[NN];
  int base = (bc_*DIi + d)*NN;
  #pragma unroll
  for (int n=0;n<NN;n++) h[n] = g_Hin[base+n];
  float Dv = Dp[d];
  __syncthreads();
  #pragma unroll 1
  for (int s=0;s<CHUNK;s++){
    int m = m0 + s;
    float dlt = g_delta[m*DIi + d];
    float x   = g_xc[m*DIi + d];
    float dx  = dlt * x;
    float y = 0.f;
    #pragma unroll
    for (int n=0;n<NN;n++){
      float dA = __expf(dlt*A[n]);
      h[n] = dA*h[n] + dx*sB[s][n];
      y += h[n]*sC[s][n];
    }
    y += Dv*x;
    float zv = g_z[m*DIi + d];
    g_yg[m*DIi + d] = y * siluf(zv);
  }
}

// ---------------- driver ----------------
extern "C" void kernel_launch(void* const* d_in, const int* in_sizes, int n_in,
                              void* d_out, int out_size){
  const float* x      = (const float*)d_in[0];
  const float* in_w   = (const float*)d_in[1];
  const float* conv_w = (const float*)d_in[2];
  const float* conv_b = (const float*)d_in[3];
  const float* A_log  = (const float*)d_in[4];
  const float* xd_w   = (const float*)d_in[5];
  const float* xB_w   = (const float*)d_in[6];
  const float* xC_w   = (const float*)d_in[7];
  const float* dtp_w  = (const float*)d_in[8];
  const float* dtp_b  = (const float*)d_in[9];
  const float* Dp     = (const float*)d_in[10];
  const float* out_w  = (const float*)d_in[11];
  const float* ln_g   = (const float*)d_in[12];
  const float* ln_b   = (const float*)d_in[13];
  const float* merge_w= (const float*)d_in[14];
  float* out = (float*)d_out;

  for (int chain=0; chain<2; chain++){
    k_init<<<MM*64/256, 256>>>(x, chain);
    for (int bi=0; bi<2; bi++){
      int blk = chain*2 + bi;
      k_ln      <<<MM/8, 256>>>(ln_g + blk*DMm, ln_b + blk*DMm);
      k_gemm_in <<<dim3(16,32), 256>>>(in_w + (size_t)blk*DMm*2*DIi);
      k_conv    <<<(MM/8)*128/256, 256>>>(conv_w + blk*DIi*4, conv_b + blk*DIi);
      k_gemm_x  <<<dim3(KS,32), 256>>>(xd_w + blk*DIi*RR,
                                       xB_w + blk*DIi*NN,
                                       xC_w + blk*DIi*NN);
      k_xred    <<<MM*16/256, 256>>>();
      k_gemm_dt <<<dim3(8,32), 256>>>(dtp_w + blk*RR*DIi, dtp_b + blk*DIi);
      k_scan1   <<<Bb*NCH, DIi>>>(A_log + blk*DIi*NN);
      k_comb    <<<64, 256>>>();
      k_scan2   <<<Bb*NCH, DIi>>>(A_log + blk*DIi*NN, Dp + blk*DIi);
      k_gemm_out<<<dim3(4,32), 256>>>(out_w + blk*DIi*DMm);
    }
    if (chain == 0) k_copy<<<MM*64/256, 256>>>();
  }
  k_merge<<<dim3(4,32), 256>>>(merge_w, out);
}

// round 4
// speedup vs baseline: 2.4030x; 1.1423x over previous
#include <cuda_runtime.h>

// ---------------- problem constants ----------------
#define Bb   2
#define Ss   2048
#define DMm  256
#define DIi  512
#define NN   16
#define RR   32
#define MM   (Bb*Ss)          // 4096 rows
#define CHUNK 32
#define NCH  (Ss/CHUNK)       // 64 chunks per sequence
#define KS   4                // split-K for x-proj

// ---------------- device scratch ----------------
__device__ float g_res [MM*DMm];
__device__ float g_fwd [MM*DMm];
__device__ float g_xn  [MM*DMm];
__device__ float g_xs  [MM*DIi];
__device__ float g_z   [MM*DIi];
__device__ float g_xc  [MM*DIi];
__device__ float g_proj[MM*64];          // [xd(32) | B(16) | C(16)]
__device__ float g_projp[KS*MM*64];      // split-K partials
__device__ float g_delta[MM*DIi];
__device__ float g_yg  [MM*DIi];
__device__ float g_P   [Bb*NCH*DIi*NN];
__device__ float g_Q   [Bb*NCH*DIi*NN];
__device__ float g_Hin [Bb*NCH*DIi*NN];

__device__ __forceinline__ float siluf(float x){ return x / (1.f + __expf(-x)); }
__device__ __forceinline__ float spf(float a){ return (a > 20.f) ? a : log1pf(__expf(a)); }

__device__ __forceinline__ unsigned tf32c(float f){
  unsigned r; asm("cvt.rna.tf32.f32 %0, %1;" : "=r"(r) : "f"(f)); return r;
}

#define MMA8(c, a, b)                                                        \
  asm volatile("mma.sync.aligned.m16n8k8.row.col.f32.tf32.tf32.f32 "         \
               "{%0,%1,%2,%3},{%4,%5,%6,%7},{%8,%9},{%0,%1,%2,%3};"          \
               : "+f"(c[0]), "+f"(c[1]), "+f"(c[2]), "+f"(c[3])              \
               : "r"(a[0]), "r"(a[1]), "r"(a[2]), "r"(a[3]),                 \
                 "r"(b[0]), "r"(b[1]))

// ---------------- init / copy ----------------
__global__ void k_init(const float* __restrict__ x, int rev){
  int idx = blockIdx.x*256 + threadIdx.x;       // MM*64 float4s
  int col = idx & 63;
  int m   = idx >> 6;
  int b = m >> 11, s = m & (Ss-1);
  int ms = rev ? (b*Ss + (Ss-1-s)) : m;
  reinterpret_cast<float4*>(g_res)[m*64+col] =
      reinterpret_cast<const float4*>(x)[ms*64+col];
}

__global__ void k_copy(){
  int idx = blockIdx.x*256 + threadIdx.x;
  reinterpret_cast<float4*>(g_fwd)[idx] = reinterpret_cast<const float4*>(g_res)[idx];
}

// ---------------- layernorm (1 warp per row of 256) ----------------
__global__ void k_ln(const float* __restrict__ g, const float* __restrict__ bt){
  int warp = (blockIdx.x*256 + threadIdx.x) >> 5;
  int lane = threadIdx.x & 31;
  const float* row = g_res + warp*DMm;
  float4 v0 = reinterpret_cast<const float4*>(row)[lane];
  float4 v1 = reinterpret_cast<const float4*>(row)[lane+32];
  float s = v0.x+v0.y+v0.z+v0.w + v1.x+v1.y+v1.z+v1.w;
  float q = v0.x*v0.x+v0.y*v0.y+v0.z*v0.z+v0.w*v0.w
          + v1.x*v1.x+v1.y*v1.y+v1.z*v1.z+v1.w*v1.w;
  #pragma unroll
  for (int o=16;o;o>>=1){ s += __shfl_xor_sync(~0u,s,o); q += __shfl_xor_sync(~0u,q,o); }
  float mean = s*(1.f/DMm);
  float var  = q*(1.f/DMm) - mean*mean;
  float r = rsqrtf(var + 1e-5f);
  float* orow = g_xn + warp*DMm;
  int c0 = lane*4, c1 = 128 + lane*4;
  float4 o0, o1;
  o0.x=(v0.x-mean)*r*g[c0+0]+bt[c0+0]; o0.y=(v0.y-mean)*r*g[c0+1]+bt[c0+1];
  o0.z=(v0.z-mean)*r*g[c0+2]+bt[c0+2]; o0.w=(v0.w-mean)*r*g[c0+3]+bt[c0+3];
  o1.x=(v1.x-mean)*r*g[c1+0]+bt[c1+0]; o1.y=(v1.y-mean)*r*g[c1+1]+bt[c1+1];
  o1.z=(v1.z-mean)*r*g[c1+2]+bt[c1+2]; o1.w=(v1.w-mean)*r*g[c1+3]+bt[c1+3];
  reinterpret_cast<float4*>(orow)[lane]    = o0;
  reinterpret_cast<float4*>(orow)[lane+32] = o1;
}

// ======================================================================
// TF32 tensor-core GEMM core, double-buffered.
// Block tile 128(M) x 64(N), 256 threads = 8 warps (4 M x 2 N).
// Warp tile 32x32 = 2 m-tiles(16) x 4 n-tiles(8), mma.m16n8k8, K-chunk 16.
// Smem holds operands PRE-PERMUTED into mma fragment order, so compute
// loads are conflict-free coalesced LDS.32 and B staging is one STS.128.
// ======================================================================
#define TC_DECL()                                                     \
  __shared__ __align__(16) unsigned Af[2][2048];                      \
  __shared__ __align__(16) unsigned Bf[2][1024];                      \
  const int t = threadIdx.x;                                          \
  const int lane = t & 31, wid = t >> 5;                              \
  const int wm = wid >> 1, wn = wid & 1;                              \
  const int s_r  = t >> 1;          /* A staging row 0..127  */       \
  const int s_kb = (t & 1) * 8;     /* A staging k base 0/8  */       \
  const int s_bq = t >> 6;          /* B staging k-quad 0..3 */       \
  const int s_bn = t & 63;          /* B staging n 0..63     */       \
  float acc[2][4][4] = {};                                            \
  float4 raA0, raA1;                                                  \
  float rb0, rb1, rb2, rb3;

#define TC_STAGE(buf) {                                               \
  int mt_ = s_r >> 4, rr_ = s_r & 15;                                 \
  int l0_ = (rr_ & 7) * 4;                                            \
  int rgb_ = rr_ >> 3;                                                \
  { int kk = s_kb;   int k8 = kk >> 3; int rg = rgb_ + ((kk & 4) ? 2 : 0); \
    *(uint4*)&Af[buf][(((mt_*2 + k8)*4 + rg)*32) + l0_] =             \
      make_uint4(tf32c(raA0.x),tf32c(raA0.y),tf32c(raA0.z),tf32c(raA0.w)); } \
  { int kk = s_kb+4; int k8 = kk >> 3; int rg = rgb_ + ((kk & 4) ? 2 : 0); \
    *(uint4*)&Af[buf][(((mt_*2 + k8)*4 + rg)*32) + l0_] =             \
      make_uint4(tf32c(raA1.x),tf32c(raA1.y),tf32c(raA1.z),tf32c(raA1.w)); } \
  { int k8_ = s_bq >> 1, rg_ = s_bq & 1;                              \
    int nt_ = s_bn >> 3, c_ = s_bn & 7;                               \
    *(uint4*)&Bf[buf][((nt_*2 + k8_)*2 + rg_)*32 + c_*4] =            \
      make_uint4(tf32c(rb0),tf32c(rb1),tf32c(rb2),tf32c(rb3)); } }

#define TC_COMP(buf)                                                  \
  _Pragma("unroll")                                                   \
  for (int k8=0;k8<2;k8++){                                           \
    unsigned a_[2][4], b_[4][2];                                      \
    _Pragma("unroll") for (int mt=0;mt<2;mt++){                       \
      int ba = (((wm*2+mt)*2 + k8)*4)*32 + lane;                      \
      a_[mt][0]=Af[buf][ba];    a_[mt][1]=Af[buf][ba+32];             \
      a_[mt][2]=Af[buf][ba+64]; a_[mt][3]=Af[buf][ba+96]; }           \
    _Pragma("unroll") for (int nt=0;nt<4;nt++){                       \
      int bb = (((wn*4+nt)*2 + k8)*2)*32 + lane;                      \
      b_[nt][0]=Bf[buf][bb]; b_[nt][1]=Bf[buf][bb+32]; }              \
    _Pragma("unroll") for (int mt=0;mt<2;mt++)                        \
      _Pragma("unroll") for (int nt=0;nt<4;nt++)                      \
        MMA8(acc[mt][nt], a_[mt], b_[nt]);                            \
  }

// double-buffered mainloop: one sync per chunk; LDG(k+2) issued before
// compute so the whole compute phase covers its latency; STS(k+1)
// overlaps mma issue.
#define TC_BODY(KT)                                                   \
  LOADA(0); LOADB(0);                                                 \
  TC_STAGE(0);                                                        \
  if (16 < (KT)) { LOADA(16); LOADB(16); }                            \
  __syncthreads();                                                    \
  { int cur = 0;                                                      \
    _Pragma("unroll 1")                                               \
    for (int k0=0; k0<(KT); k0+=16){                                  \
      if (k0+16 < (KT)) TC_STAGE(cur^1);                              \
      if (k0+32 < (KT)) { LOADA(k0+32); LOADB(k0+32); }               \
      TC_COMP(cur);                                                   \
      __syncthreads();                                                \
      cur ^= 1;                                                       \
    } }

// in_proj: xn[4096,256] @ in_w[256,1024] -> xs | z
__global__ void k_gemm_in(const float* __restrict__ W){
  int col0 = blockIdx.x*64, row0 = blockIdx.y*128;
  TC_DECL();
#define LOADA(k0_) { raA0 = *(const float4*)&g_xn[(row0+s_r)*DMm + (k0_)+s_kb];    \
                     raA1 = *(const float4*)&g_xn[(row0+s_r)*DMm + (k0_)+s_kb+4]; }
#define LOADB(k0_) { int kb_ = (k0_) + s_bq*4;                                     \
                     rb0 = W[(size_t)(kb_+0)*(2*DIi) + col0 + s_bn];               \
                     rb1 = W[(size_t)(kb_+1)*(2*DIi) + col0 + s_bn];               \
                     rb2 = W[(size_t)(kb_+2)*(2*DIi) + col0 + s_bn];               \
                     rb3 = W[(size_t)(kb_+3)*(2*DIi) + col0 + s_bn]; }
  TC_BODY(DMm);
#undef LOADA
#undef LOADB
  float* dst = (col0 < DIi) ? g_xs : g_z;
  int cb = (col0 < DIi) ? col0 : col0 - DIi;
  #pragma unroll
  for (int mt=0;mt<2;mt++)
    #pragma unroll
    for (int nt=0;nt<4;nt++){
      int r = row0 + wm*32 + mt*16 + (lane>>2);
      int c = cb + wn*32 + nt*8 + (lane&3)*2;
      *(float2*)&dst[(size_t)r*DIi + c]     = make_float2(acc[mt][nt][0], acc[mt][nt][1]);
      *(float2*)&dst[(size_t)(r+8)*DIi + c] = make_float2(acc[mt][nt][2], acc[mt][nt][3]);
    }
}

// x-proj split-K: xc[4096,512] @ [xd(32)|xB(16)|xC(16)] -> projp[kz]
__global__ void k_gemm_x(const float* __restrict__ xdw,
                         const float* __restrict__ xbw,
                         const float* __restrict__ xcw){
  int kz = blockIdx.x, row0 = blockIdx.y*128;
  int kbase = kz*(DIi/KS);
  TC_DECL();
  const float* bsrc; int ldb, boff;
  if      (s_bn < 32){ bsrc = xdw; ldb = 32; boff = s_bn;      }
  else if (s_bn < 48){ bsrc = xbw; ldb = 16; boff = s_bn - 32; }
  else               { bsrc = xcw; ldb = 16; boff = s_bn - 48; }
#define LOADA(k0_) { raA0 = *(const float4*)&g_xc[(row0+s_r)*DIi + kbase+(k0_)+s_kb];    \
                     raA1 = *(const float4*)&g_xc[(row0+s_r)*DIi + kbase+(k0_)+s_kb+4]; }
#define LOADB(k0_) { int kb_ = kbase + (k0_) + s_bq*4;                                   \
                     rb0 = bsrc[(kb_+0)*ldb + boff];                                     \
                     rb1 = bsrc[(kb_+1)*ldb + boff];                                     \
                     rb2 = bsrc[(kb_+2)*ldb + boff];                                     \
                     rb3 = bsrc[(kb_+3)*ldb + boff]; }
  TC_BODY(DIi/KS);
#undef LOADA
#undef LOADB
  float* dst = g_projp + (size_t)kz*MM*64;
  #pragma unroll
  for (int mt=0;mt<2;mt++)
    #pragma unroll
    for (int nt=0;nt<4;nt++){
      int r = row0 + wm*32 + mt*16 + (lane>>2);
      int c = wn*32 + nt*8 + (lane&3)*2;
      *(float2*)&dst[r*64 + c]     = make_float2(acc[mt][nt][0], acc[mt][nt][1]);
      *(float2*)&dst[(r+8)*64 + c] = make_float2(acc[mt][nt][2], acc[mt][nt][3]);
    }
}

__global__ void k_xred(){
  int i = blockIdx.x*256 + threadIdx.x;   // MM*16 float4s
  float4 a = reinterpret_cast<const float4*>(g_projp)[i];
  float4 b = reinterpret_cast<const float4*>(g_projp + MM*64)[i];
  float4 c = reinterpret_cast<const float4*>(g_projp + 2*MM*64)[i];
  float4 d = reinterpret_cast<const float4*>(g_projp + 3*MM*64)[i];
  reinterpret_cast<float4*>(g_proj)[i] =
      make_float4(a.x+b.x+c.x+d.x, a.y+b.y+c.y+d.y,
                  a.z+b.z+c.z+d.z, a.w+b.w+c.w+d.w);
}

// delta: softplus(proj[:, :32] @ dtp_w[32,512] + dtp_b) -> g_delta
__global__ void k_gemm_dt(const float* __restrict__ Wd, const float* __restrict__ bd){
  int col0 = blockIdx.x*64, row0 = blockIdx.y*128;
  TC_DECL();
#define LOADA(k0_) { raA0 = *(const float4*)&g_proj[(row0+s_r)*64 + (k0_)+s_kb];    \
                     raA1 = *(const float4*)&g_proj[(row0+s_r)*64 + (k0_)+s_kb+4]; }
#define LOADB(k0_) { int kb_ = (k0_) + s_bq*4;                                      \
                     rb0 = Wd[(kb_+0)*DIi + col0 + s_bn];                           \
                     rb1 = Wd[(kb_+1)*DIi + col0 + s_bn];                           \
                     rb2 = Wd[(kb_+2)*DIi + col0 + s_bn];                           \
                     rb3 = Wd[(kb_+3)*DIi + col0 + s_bn]; }
  TC_BODY(RR);
#undef LOADA
#undef LOADB
  #pragma unroll
  for (int mt=0;mt<2;mt++)
    #pragma unroll
    for (int nt=0;nt<4;nt++){
      int r = row0 + wm*32 + mt*16 + (lane>>2);
      int c = col0 + wn*32 + nt*8 + (lane&3)*2;
      float b0 = bd[c], b1 = bd[c+1];
      *(float2*)&g_delta[(size_t)r*DIi + c] =
          make_float2(spf(acc[mt][nt][0]+b0), spf(acc[mt][nt][1]+b1));
      *(float2*)&g_delta[(size_t)(r+8)*DIi + c] =
          make_float2(spf(acc[mt][nt][2]+b0), spf(acc[mt][nt][3]+b1));
    }
}

// out_proj: yg[4096,512] @ out_w[512,256] + residual (in place on g_res)
__global__ void k_gemm_out(const float* __restrict__ W){
  int col0 = blockIdx.x*64, row0 = blockIdx.y*128;
  TC_DECL();
#define LOADA(k0_) { raA0 = *(const float4*)&g_yg[(row0+s_r)*DIi + (k0_)+s_kb];    \
                     raA1 = *(const float4*)&g_yg[(row0+s_r)*DIi + (k0_)+s_kb+4]; }
#define LOADB(k0_) { int kb_ = (k0_) + s_bq*4;                                     \
                     rb0 = W[(kb_+0)*DMm + col0 + s_bn];                           \
                     rb1 = W[(kb_+1)*DMm + col0 + s_bn];                           \
                     rb2 = W[(kb_+2)*DMm + col0 + s_bn];                           \
                     rb3 = W[(kb_+3)*DMm + col0 + s_bn]; }
  TC_BODY(DIi);
#undef LOADA
#undef LOADB
  #pragma unroll
  for (int mt=0;mt<2;mt++)
    #pragma unroll
    for (int nt=0;nt<4;nt++){
      int r = row0 + wm*32 + mt*16 + (lane>>2);
      int c = col0 + wn*32 + nt*8 + (lane&3)*2;
      float2 o0 = *(const float2*)&g_res[(size_t)r*DMm + c];
      float2 o1 = *(const float2*)&g_res[(size_t)(r+8)*DMm + c];
      *(float2*)&g_res[(size_t)r*DMm + c] =
          make_float2(acc[mt][nt][0]+o0.x, acc[mt][nt][1]+o0.y);
      *(float2*)&g_res[(size_t)(r+8)*DMm + c] =
          make_float2(acc[mt][nt][2]+o1.x, acc[mt][nt][3]+o1.y);
    }
}

// merge: concat(fwd, res_reversed)[4096,512] @ merge_w[512,256] -> out
__global__ void k_merge(const float* __restrict__ W, float* __restrict__ out){
  int col0 = blockIdx.x*64, row0 = blockIdx.y*128;
  TC_DECL();
  int r_ = row0 + s_r;
  int b_ = r_ >> 11, s_ = r_ & (Ss-1);
  int rrev = b_*Ss + (Ss-1-s_);
#define LOADA(k0_) {                                                               \
    int kk0 = (k0_)+s_kb, kk1 = (k0_)+s_kb+4;                                      \
    raA0 = *(const float4*)((kk0 < DMm) ? (g_fwd + r_*DMm + kk0)                   \
                                        : (g_res + rrev*DMm + kk0-DMm));           \
    raA1 = *(const float4*)((kk1 < DMm) ? (g_fwd + r_*DMm + kk1)                   \
                                        : (g_res + rrev*DMm + kk1-DMm)); }
#define LOADB(k0_) { int kb_ = (k0_) + s_bq*4;                                     \
                     rb0 = W[(kb_+0)*DMm + col0 + s_bn];                           \
                     rb1 = W[(kb_+1)*DMm + col0 + s_bn];                           \
                     rb2 = W[(kb_+2)*DMm + col0 + s_bn];                           \
                     rb3 = W[(kb_+3)*DMm + col0 + s_bn]; }
  TC_BODY(2*DMm);
#undef LOADA
#undef LOADB
  #pragma unroll
  for (int mt=0;mt<2;mt++)
    #pragma unroll
    for (int nt=0;nt<4;nt++){
      int r = row0 + wm*32 + mt*16 + (lane>>2);
      int c = col0 + wn*32 + nt*8 + (lane&3)*2;
      *(float2*)&out[(size_t)r*DMm + c]     = make_float2(acc[mt][nt][0], acc[mt][nt][1]);
      *(float2*)&out[(size_t)(r+8)*DMm + c] = make_float2(acc[mt][nt][2], acc[mt][nt][3]);
    }
}

// ---------------- causal depthwise conv (K=4) + silu, 4 s-positions/thread ----------------
__global__ void k_conv(const float* __restrict__ cw, const float* __restrict__ cb){
  int idx = blockIdx.x*256 + threadIdx.x;   // (MM/4)*128
  int d4 = idx & 127, g = idx >> 7;         // g in [0, MM/4)
  int b = g >> 9, sg = g & 511;
  int m0 = b*Ss + sg*4;
  int d = d4*4;
  float4 w0 = *(const float4*)(cw + (d+0)*4);
  float4 w1 = *(const float4*)(cw + (d+1)*4);
  float4 w2 = *(const float4*)(cw + (d+2)*4);
  float4 w3 = *(const float4*)(cw + (d+3)*4);
  float4 bv = *(const float4*)(cb + d);
  float4 x0, x1, x2;
  if (sg > 0){
    x0 = *(const float4*)&g_xs[(m0-3)*DIi + d];
    x1 = *(const float4*)&g_xs[(m0-2)*DIi + d];
    x2 = *(const float4*)&g_xs[(m0-1)*DIi + d];
  } else {
    x0 = x1 = x2 = make_float4(0.f,0.f,0.f,0.f);
  }
  #pragma unroll
  for (int s=0;s<4;s++){
    float4 x3 = *(const float4*)&g_xs[(m0+s)*DIi + d];
    float4 a;
    a.x = bv.x + w0.x*x0.x + w0.y*x1.x + w0.z*x2.x + w0.w*x3.x;
    a.y = bv.y + w1.x*x0.y + w1.y*x1.y + w1.z*x2.y + w1.w*x3.y;
    a.z = bv.z + w2.x*x0.z + w2.y*x1.z + w2.z*x2.z + w2.w*x3.z;
    a.w = bv.w + w3.x*x0.w + w3.y*x1.w + w3.z*x2.w + w3.w*x3.w;
    a.x = siluf(a.x); a.y = siluf(a.y); a.z = siluf(a.z); a.w = siluf(a.w);
    *(float4*)&g_xc[(m0+s)*DIi + d] = a;
    x0 = x1; x1 = x2; x2 = x3;
  }
}

// ---------------- chunked scan phase 1 (256 threads, half channels per block) ----------------
__global__ void k_scan1(const float* __restrict__ Alog){
  __shared__ float sB[CHUNK][NN];
  int blk = blockIdx.x;               // 2 * Bb*NCH
  int bc_ = blk >> 1;
  int b = bc_ >> 6, c = bc_ & 63;
  int d = (blk & 1)*256 + threadIdx.x;
  int m0 = b*Ss + c*CHUNK;
  { int i0 = threadIdx.x, i1 = threadIdx.x + 256;
    sB[i0>>4][i0&15] = g_proj[(m0+(i0>>4))*64 + 32 + (i0&15)];
    sB[i1>>4][i1&15] = g_proj[(m0+(i1>>4))*64 + 32 + (i1&15)]; }
  float A[NN];
  #pragma unroll
  for (int n=0;n<NN;n++) A[n] = -__expf(Alog[d*NN + n]);
  __syncthreads();
  float h[NN];
  #pragma unroll
  for (int n=0;n<NN;n++) h[n] = 0.f;
  float sd = 0.f;
  #pragma unroll 1
  for (int s=0;s<CHUNK;s++){
    int m = m0 + s;
    float dlt = g_delta[m*DIi + d];
    float dx  = dlt * g_xc[m*DIi + d];
    sd += dlt;
    #pragma unroll
    for (int n=0;n<NN;n++){
      float dA = __expf(dlt*A[n]);
      h[n] = dA*h[n] + dx*sB[s][n];
    }
  }
  int base = (bc_*DIi + d)*NN;
  #pragma unroll
  for (int n=0;n<NN;n++){ g_Q[base+n]=h[n]; g_P[base+n]=__expf(sd*A[n]); }
}

// ---------------- phase 2: combine across chunks ----------------
__global__ void k_comb(){
  int i = blockIdx.x*128 + threadIdx.x;     // Bb*DIi*NN = 16384
  int n = i & 15, d = (i >> 4) & (DIi-1), b = i >> 13;
  float H = 0.f;
  for (int c=0;c<NCH;c++){
    int idx = ((b*NCH+c)*DIi + d)*NN + n;
    g_Hin[idx] = H;
    H = g_P[idx]*H + g_Q[idx];
  }
}

// ---------------- phase 3: replay + gated output ----------------
__global__ void k_scan2(const float* __restrict__ Alog, const float* __restrict__ Dp){
  __shared__ float sB[CHUNK][NN];
  __shared__ float sC[CHUNK][NN];
  int blk = blockIdx.x;
  int bc_ = blk >> 1;
  int b = bc_ >> 6, c = bc_ & 63;
  int d = (blk & 1)*256 + threadIdx.x;
  int m0 = b*Ss + c*CHUNK;
  { int i0 = threadIdx.x, i1 = threadIdx.x + 256;
    sB[i0>>4][i0&15] = g_proj[(m0+(i0>>4))*64 + 32 + (i0&15)];
    sB[i1>>4][i1&15] = g_proj[(m0+(i1>>4))*64 + 32 + (i1&15)];
    sC[i0>>4][i0&15] = g_proj[(m0+(i0>>4))*64 + 48 + (i0&15)];
    sC[i1>>4][i1&15] = g_proj[(m0+(i1>>4))*64 + 48 + (i1&15)]; }
  float A[NN];
  #pragma unroll
  for (int n=0;n<NN;n++) A[n] = -__expf(Alog[d*NN + n]);
  float h[NN];
  int base = (bc_*DIi + d)*NN;
  #pragma unroll
  for (int n=0;n<NN;n++) h[n] = g_Hin[base+n];
  float Dv = Dp[d];
  __syncthreads();
  #pragma unroll 1
  for (int s=0;s<CHUNK;s++){
    int m = m0 + s;
    float dlt = g_delta[m*DIi + d];
    float x   = g_xc[m*DIi + d];
    float dx  = dlt * x;
    float y = 0.f;
    #pragma unroll
    for (int n=0;n<NN;n++){
      float dA = __expf(dlt*A[n]);
      h[n] = dA*h[n] + dx*sB[s][n];
      y += h[n]*sC[s][n];
    }
    y += Dv*x;
    float zv = g_z[m*DIi + d];
    g_yg[m*DIi + d] = y * siluf(zv);
  }
}

// ---------------- driver ----------------
extern "C" void kernel_launch(void* const* d_in, const int* in_sizes, int n_in,
                              void* d_out, int out_size){
  const float* x      = (const float*)d_in[0];
  const float* in_w   = (const float*)d_in[1];
  const float* conv_w = (const float*)d_in[2];
  const float* conv_b = (const float*)d_in[3];
  const float* A_log  = (const float*)d_in[4];
  const float* xd_w   = (const float*)d_in[5];
  const float* xB_w   = (const float*)d_in[6];
  const float* xC_w   = (const float*)d_in[7];
  const float* dtp_w  = (const float*)d_in[8];
  const float* dtp_b  = (const float*)d_in[9];
  const float* Dp     = (const float*)d_in[10];
  const float* out_w  = (const float*)d_in[11];
  const float* ln_g   = (const float*)d_in[12];
  const float* ln_b   = (const float*)d_in[13];
  const float* merge_w= (const float*)d_in[14];
  float* out = (float*)d_out;

  for (int chain=0; chain<2; chain++){
    k_init<<<MM*64/256, 256>>>(x, chain);
    for (int bi=0; bi<2; bi++){
      int blk = chain*2 + bi;
      k_ln      <<<MM/8, 256>>>(ln_g + blk*DMm, ln_b + blk*DMm);
      k_gemm_in <<<dim3(16,32), 256>>>(in_w + (size_t)blk*DMm*2*DIi);
      k_conv    <<<(MM/4)*128/256, 256>>>(conv_w + blk*DIi*4, conv_b + blk*DIi);
      k_gemm_x  <<<dim3(KS,32), 256>>>(xd_w + blk*DIi*RR,
                                       xB_w + blk*DIi*NN,
                                       xC_w + blk*DIi*NN);
      k_xred    <<<MM*16/256, 256>>>();
      k_gemm_dt <<<dim3(8,32), 256>>>(dtp_w + blk*RR*DIi, dtp_b + blk*DIi);
      k_scan1   <<<2*Bb*NCH, 256>>>(A_log + blk*DIi*NN);
      k_comb    <<<128, 128>>>();
      k_scan2   <<<2*Bb*NCH, 256>>>(A_log + blk*DIi*NN, Dp + blk*DIi);
      k_gemm_out<<<dim3(4,32), 256>>>(out_w + blk*DIi*DMm);
    }
    if (chain == 0) k_copy<<<MM*64/256, 256>>>();
  }
  k_merge<<<dim3(4,32), 256>>>(merge_w, out);
}

// round 5
// speedup vs baseline: 2.6172x; 1.0891x over previous
#include <cuda_runtime.h>
#include <cuda_fp16.h>

// ---------------- problem constants ----------------
#define Bb   2
#define Ss   2048
#define DMm  256
#define DIi  512
#define NN   16
#define RR   32
#define MM   (Bb*Ss)          // 4096 rows
#define CHUNK 32
#define NCH  (Ss/CHUNK)       // 64 chunks per sequence
#define KS   4                // split-K for x-proj

// ---------------- device scratch ----------------
__device__ float g_res [MM*DMm];
__device__ float g_fwd [MM*DMm];
__device__ float g_xn  [MM*DMm];
__device__ float g_xs  [MM*DIi];
__device__ float g_z   [MM*DIi];
__device__ float g_xc  [MM*DIi];
__device__ float g_proj[MM*64];          // [xd(32) | B(16) | C(16)]
__device__ float g_projp[KS*MM*64];      // split-K partials
__device__ float g_delta[MM*DIi];
__device__ float g_yg  [MM*DIi];
__device__ float g_P   [Bb*NCH*DIi*NN];
__device__ float g_Q   [Bb*NCH*DIi*NN];
__device__ float g_Hin [Bb*NCH*DIi*NN];

__device__ __forceinline__ float siluf(float x){ return x / (1.f + __expf(-x)); }
__device__ __forceinline__ float spf(float a){ return (a > 20.f) ? a : log1pf(__expf(a)); }

__device__ __forceinline__ unsigned h2pack(float a, float b){
  __half2 h = __floats2half2_rn(a, b);
  return *reinterpret_cast<unsigned*>(&h);
}

#define MMA16(c, a, b)                                                       \
  asm volatile("mma.sync.aligned.m16n8k16.row.col.f32.f16.f16.f32 "          \
               "{%0,%1,%2,%3},{%4,%5,%6,%7},{%8,%9},{%0,%1,%2,%3};"          \
               : "+f"(c[0]), "+f"(c[1]), "+f"(c[2]), "+f"(c[3])              \
               : "r"(a[0]), "r"(a[1]), "r"(a[2]), "r"(a[3]),                 \
                 "r"(b[0]), "r"(b[1]))

// ---------------- init / copy ----------------
__global__ void k_init(const float* __restrict__ x, int rev){
  int idx = blockIdx.x*256 + threadIdx.x;       // MM*64 float4s
  int col = idx & 63;
  int m   = idx >> 6;
  int b = m >> 11, s = m & (Ss-1);
  int ms = rev ? (b*Ss + (Ss-1-s)) : m;
  reinterpret_cast<float4*>(g_res)[m*64+col] =
      reinterpret_cast<const float4*>(x)[ms*64+col];
}

__global__ void k_copy(){
  int idx = blockIdx.x*256 + threadIdx.x;
  reinterpret_cast<float4*>(g_fwd)[idx] = reinterpret_cast<const float4*>(g_res)[idx];
}

// ---------------- layernorm (1 warp per row of 256) ----------------
__global__ void k_ln(const float* __restrict__ g, const float* __restrict__ bt){
  int warp = (blockIdx.x*256 + threadIdx.x) >> 5;
  int lane = threadIdx.x & 31;
  const float* row = g_res + warp*DMm;
  float4 v0 = reinterpret_cast<const float4*>(row)[lane];
  float4 v1 = reinterpret_cast<const float4*>(row)[lane+32];
  float s = v0.x+v0.y+v0.z+v0.w + v1.x+v1.y+v1.z+v1.w;
  float q = v0.x*v0.x+v0.y*v0.y+v0.z*v0.z+v0.w*v0.w
          + v1.x*v1.x+v1.y*v1.y+v1.z*v1.z+v1.w*v1.w;
  #pragma unroll
  for (int o=16;o;o>>=1){ s += __shfl_xor_sync(~0u,s,o); q += __shfl_xor_sync(~0u,q,o); }
  float mean = s*(1.f/DMm);
  float var  = q*(1.f/DMm) - mean*mean;
  float r = rsqrtf(var + 1e-5f);
  float* orow = g_xn + warp*DMm;
  int c0 = lane*4, c1 = 128 + lane*4;
  float4 o0, o1;
  o0.x=(v0.x-mean)*r*g[c0+0]+bt[c0+0]; o0.y=(v0.y-mean)*r*g[c0+1]+bt[c0+1];
  o0.z=(v0.z-mean)*r*g[c0+2]+bt[c0+2]; o0.w=(v0.w-mean)*r*g[c0+3]+bt[c0+3];
  o1.x=(v1.x-mean)*r*g[c1+0]+bt[c1+0]; o1.y=(v1.y-mean)*r*g[c1+1]+bt[c1+1];
  o1.z=(v1.z-mean)*r*g[c1+2]+bt[c1+2]; o1.w=(v1.w-mean)*r*g[c1+3]+bt[c1+3];
  reinterpret_cast<float4*>(orow)[lane]    = o0;
  reinterpret_cast<float4*>(orow)[lane+32] = o1;
}

// ======================================================================
// FP16 tensor-core GEMM core, double-buffered, mma.m16n8k16.
// Block tile 128(M) x 64(N), 256 threads = 8 warps (4 M x 2 N),
// warp tile 32x32 = 2 mt x 4 nt. K-chunk = 16 = one mma k-step.
// Smem holds fragments per-lane contiguous:
//   Af[mt(8)][lane(32)][4 regs]  -> one LDS.128 per mt  (conflict-free)
//   Bf[nt(8)][lane(32)][2 regs]  -> one LDS.64  per nt  (conflict-free)
// ======================================================================
#define TC_DECL()                                                     \
  __shared__ __align__(16) unsigned Af[2][1024];                      \
  __shared__ __align__(16) unsigned Bf[2][512];                       \
  const int t = threadIdx.x;                                          \
  const int lane = t & 31, wid = t >> 5;                              \
  const int wm = wid >> 1, wn = wid & 1;                              \
  const int s_r  = t >> 1;          /* A staging row 0..127  */       \
  const int s_kb = (t & 1) * 8;     /* A staging k base 0/8  */       \
  const int s_bq = t >> 6;          /* B staging k-quad 0..3 */       \
  const int s_bn = t & 63;          /* B staging n 0..63     */       \
  float acc[2][4][4] = {};                                            \
  float4 raA0, raA1;                                                  \
  float rb0, rb1, rb2, rb3;

#define TC_STAGE(buf) {                                               \
  int mt_ = s_r >> 4, rr_ = s_r & 15;                                 \
  int lb_ = (rr_ & 7) * 4;                                            \
  int rg_ = (rr_ >> 3) + ((s_kb >> 2) & 2);                           \
  unsigned* ab = &Af[buf][(mt_*32 + lb_)*4 + rg_];                    \
  ab[0]  = h2pack(raA0.x, raA0.y);                                    \
  ab[4]  = h2pack(raA0.z, raA0.w);                                    \
  ab[8]  = h2pack(raA1.x, raA1.y);                                    \
  ab[12] = h2pack(raA1.z, raA1.w);                                    \
  { int ln0 = (s_bn & 7)*4 + ((2*s_bq) & 3);                          \
    int rgB = s_bq >> 1;                                              \
    unsigned* bb = &Bf[buf][((s_bn >> 3)*32 + ln0)*2 + rgB];          \
    bb[0] = h2pack(rb0, rb1);                                         \
    bb[2] = h2pack(rb2, rb3); } }

#define TC_COMP(buf) {                                                \
  unsigned a_[2][4]; unsigned b_[4][2];                               \
  _Pragma("unroll") for (int mt=0;mt<2;mt++)                          \
    *(uint4*)a_[mt] = *(const uint4*)&Af[buf][((wm*2+mt)*32 + lane)*4]; \
  _Pragma("unroll") for (int nt=0;nt<4;nt++)                          \
    *(uint2*)b_[nt] = *(const uint2*)&Bf[buf][((wn*4+nt)*32 + lane)*2]; \
  _Pragma("unroll") for (int mt=0;mt<2;mt++)                          \
    _Pragma("unroll") for (int nt=0;nt<4;nt++)                        \
      MMA16(acc[mt][nt], a_[mt], b_[nt]); }

// double-buffered mainloop: one sync per chunk; LDG(k+2) issued before
// compute so the whole compute phase covers its latency; STS(k+1)
// overlaps mma issue.
#define TC_BODY(KT)                                                   \
  LOADA(0); LOADB(0);                                                 \
  TC_STAGE(0);                                                        \
  if (16 < (KT)) { LOADA(16); LOADB(16); }                            \
  __syncthreads();                                                    \
  { int cur = 0;                                                      \
    _Pragma("unroll 1")                                               \
    for (int k0=0; k0<(KT); k0+=16){                                  \
      if (k0+16 < (KT)) TC_STAGE(cur^1);                              \
      if (k0+32 < (KT)) { LOADA(k0+32); LOADB(k0+32); }               \
      TC_COMP(cur);                                                   \
      __syncthreads();                                                \
      cur ^= 1;                                                       \
    } }

// in_proj: xn[4096,256] @ in_w[256,1024] -> xs | z
__global__ void k_gemm_in(const float* __restrict__ W){
  int col0 = blockIdx.x*64, row0 = blockIdx.y*128;
  TC_DECL();
#define LOADA(k0_) { raA0 = *(const float4*)&g_xn[(row0+s_r)*DMm + (k0_)+s_kb];    \
                     raA1 = *(const float4*)&g_xn[(row0+s_r)*DMm + (k0_)+s_kb+4]; }
#define LOADB(k0_) { int kb_ = (k0_) + s_bq*4;                                     \
                     rb0 = W[(size_t)(kb_+0)*(2*DIi) + col0 + s_bn];               \
                     rb1 = W[(size_t)(kb_+1)*(2*DIi) + col0 + s_bn];               \
                     rb2 = W[(size_t)(kb_+2)*(2*DIi) + col0 + s_bn];               \
                     rb3 = W[(size_t)(kb_+3)*(2*DIi) + col0 + s_bn]; }
  TC_BODY(DMm);
#undef LOADA
#undef LOADB
  float* dst = (col0 < DIi) ? g_xs : g_z;
  int cb = (col0 < DIi) ? col0 : col0 - DIi;
  #pragma unroll
  for (int mt=0;mt<2;mt++)
    #pragma unroll
    for (int nt=0;nt<4;nt++){
      int r = row0 + wm*32 + mt*16 + (lane>>2);
      int c = cb + wn*32 + nt*8 + (lane&3)*2;
      *(float2*)&dst[(size_t)r*DIi + c]     = make_float2(acc[mt][nt][0], acc[mt][nt][1]);
      *(float2*)&dst[(size_t)(r+8)*DIi + c] = make_float2(acc[mt][nt][2], acc[mt][nt][3]);
    }
}

// x-proj split-K: xc[4096,512] @ [xd(32)|xB(16)|xC(16)] -> projp[kz]
__global__ void k_gemm_x(const float* __restrict__ xdw,
                         const float* __restrict__ xbw,
                         const float* __restrict__ xcw){
  int kz = blockIdx.x, row0 = blockIdx.y*128;
  int kbase = kz*(DIi/KS);
  TC_DECL();
  const float* bsrc; int ldb, boff;
  if      (s_bn < 32){ bsrc = xdw; ldb = 32; boff = s_bn;      }
  else if (s_bn < 48){ bsrc = xbw; ldb = 16; boff = s_bn - 32; }
  else               { bsrc = xcw; ldb = 16; boff = s_bn - 48; }
#define LOADA(k0_) { raA0 = *(const float4*)&g_xc[(row0+s_r)*DIi + kbase+(k0_)+s_kb];    \
                     raA1 = *(const float4*)&g_xc[(row0+s_r)*DIi + kbase+(k0_)+s_kb+4]; }
#define LOADB(k0_) { int kb_ = kbase + (k0_) + s_bq*4;                                   \
                     rb0 = bsrc[(kb_+0)*ldb + boff];                                     \
                     rb1 = bsrc[(kb_+1)*ldb + boff];                                     \
                     rb2 = bsrc[(kb_+2)*ldb + boff];                                     \
                     rb3 = bsrc[(kb_+3)*ldb + boff]; }
  TC_BODY(DIi/KS);
#undef LOADA
#undef LOADB
  float* dst = g_projp + (size_t)kz*MM*64;
  #pragma unroll
  for (int mt=0;mt<2;mt++)
    #pragma unroll
    for (int nt=0;nt<4;nt++){
      int r = row0 + wm*32 + mt*16 + (lane>>2);
      int c = wn*32 + nt*8 + (lane&3)*2;
      *(float2*)&dst[r*64 + c]     = make_float2(acc[mt][nt][0], acc[mt][nt][1]);
      *(float2*)&dst[(r+8)*64 + c] = make_float2(acc[mt][nt][2], acc[mt][nt][3]);
    }
}

__global__ void k_xred(){
  int i = blockIdx.x*256 + threadIdx.x;   // MM*16 float4s
  float4 a = reinterpret_cast<const float4*>(g_projp)[i];
  float4 b = reinterpret_cast<const float4*>(g_projp + MM*64)[i];
  float4 c = reinterpret_cast<const float4*>(g_projp + 2*MM*64)[i];
  float4 d = reinterpret_cast<const float4*>(g_projp + 3*MM*64)[i];
  reinterpret_cast<float4*>(g_proj)[i] =
      make_float4(a.x+b.x+c.x+d.x, a.y+b.y+c.y+d.y,
                  a.z+b.z+c.z+d.z, a.w+b.w+c.w+d.w);
}

// delta: softplus(proj[:, :32] @ dtp_w[32,512] + dtp_b) -> g_delta
__global__ void k_gemm_dt(const float* __restrict__ Wd, const float* __restrict__ bd){
  int col0 = blockIdx.x*64, row0 = blockIdx.y*128;
  TC_DECL();
#define LOADA(k0_) { raA0 = *(const float4*)&g_proj[(row0+s_r)*64 + (k0_)+s_kb];    \
                     raA1 = *(const float4*)&g_proj[(row0+s_r)*64 + (k0_)+s_kb+4]; }
#define LOADB(k0_) { int kb_ = (k0_) + s_bq*4;                                      \
                     rb0 = Wd[(kb_+0)*DIi + col0 + s_bn];                           \
                     rb1 = Wd[(kb_+1)*DIi + col0 + s_bn];                           \
                     rb2 = Wd[(kb_+2)*DIi + col0 + s_bn];                           \
                     rb3 = Wd[(kb_+3)*DIi + col0 + s_bn]; }
  TC_BODY(RR);
#undef LOADA
#undef LOADB
  #pragma unroll
  for (int mt=0;mt<2;mt++)
    #pragma unroll
    for (int nt=0;nt<4;nt++){
      int r = row0 + wm*32 + mt*16 + (lane>>2);
      int c = col0 + wn*32 + nt*8 + (lane&3)*2;
      float b0 = bd[c], b1 = bd[c+1];
      *(float2*)&g_delta[(size_t)r*DIi + c] =
          make_float2(spf(acc[mt][nt][0]+b0), spf(acc[mt][nt][1]+b1));
      *(float2*)&g_delta[(size_t)(r+8)*DIi + c] =
          make_float2(spf(acc[mt][nt][2]+b0), spf(acc[mt][nt][3]+b1));
    }
}

// out_proj: yg[4096,512] @ out_w[512,256] + residual (in place on g_res)
__global__ void k_gemm_out(const float* __restrict__ W){
  int col0 = blockIdx.x*64, row0 = blockIdx.y*128;
  TC_DECL();
#define LOADA(k0_) { raA0 = *(const float4*)&g_yg[(row0+s_r)*DIi + (k0_)+s_kb];    \
                     raA1 = *(const float4*)&g_yg[(row0+s_r)*DIi + (k0_)+s_kb+4]; }
#define LOADB(k0_) { int kb_ = (k0_) + s_bq*4;                                     \
                     rb0 = W[(kb_+0)*DMm + col0 + s_bn];                           \
                     rb1 = W[(kb_+1)*DMm + col0 + s_bn];                           \
                     rb2 = W[(kb_+2)*DMm + col0 + s_bn];                           \
                     rb3 = W[(kb_+3)*DMm + col0 + s_bn]; }
  TC_BODY(DIi);
#undef LOADA
#undef LOADB
  #pragma unroll
  for (int mt=0;mt<2;mt++)
    #pragma unroll
    for (int nt=0;nt<4;nt++){
      int r = row0 + wm*32 + mt*16 + (lane>>2);
      int c = col0 + wn*32 + nt*8 + (lane&3)*2;
      float2 o0 = *(const float2*)&g_res[(size_t)r*DMm + c];
      float2 o1 = *(const float2*)&g_res[(size_t)(r+8)*DMm + c];
      *(float2*)&g_res[(size_t)r*DMm + c] =
          make_float2(acc[mt][nt][0]+o0.x, acc[mt][nt][1]+o0.y);
      *(float2*)&g_res[(size_t)(r+8)*DMm + c] =
          make_float2(acc[mt][nt][2]+o1.x, acc[mt][nt][3]+o1.y);
    }
}

// merge: concat(fwd, res_reversed)[4096,512] @ merge_w[512,256] -> out
__global__ void k_merge(const float* __restrict__ W, float* __restrict__ out){
  int col0 = blockIdx.x*64, row0 = blockIdx.y*128;
  TC_DECL();
  int r_ = row0 + s_r;
  int b_ = r_ >> 11, s_ = r_ & (Ss-1);
  int rrev = b_*Ss + (Ss-1-s_);
#define LOADA(k0_) {                                                               \
    int kk0 = (k0_)+s_kb, kk1 = (k0_)+s_kb+4;                                      \
    raA0 = *(const float4*)((kk0 < DMm) ? (g_fwd + r_*DMm + kk0)                   \
                                        : (g_res + rrev*DMm + kk0-DMm));           \
    raA1 = *(const float4*)((kk1 < DMm) ? (g_fwd + r_*DMm + kk1)                   \
                                        : (g_res + rrev*DMm + kk1-DMm)); }
#define LOADB(k0_) { int kb_ = (k0_) + s_bq*4;                                     \
                     rb0 = W[(kb_+0)*DMm + col0 + s_bn];                           \
                     rb1 = W[(kb_+1)*DMm + col0 + s_bn];                           \
                     rb2 = W[(kb_+2)*DMm + col0 + s_bn];                           \
                     rb3 = W[(kb_+3)*DMm + col0 + s_bn]; }
  TC_BODY(2*DMm);
#undef LOADA
#undef LOADB
  #pragma unroll
  for (int mt=0;mt<2;mt++)
    #pragma unroll
    for (int nt=0;nt<4;nt++){
      int r = row0 + wm*32 + mt*16 + (lane>>2);
      int c = col0 + wn*32 + nt*8 + (lane&3)*2;
      *(float2*)&out[(size_t)r*DMm + c]     = make_float2(acc[mt][nt][0], acc[mt][nt][1]);
      *(float2*)&out[(size_t)(r+8)*DMm + c] = make_float2(acc[mt][nt][2], acc[mt][nt][3]);
    }
}

// ---------------- causal depthwise conv (K=4) + silu, 4 s-positions/thread ----------------
__global__ void k_conv(const float* __restrict__ cw, const float* __restrict__ cb){
  int idx = blockIdx.x*256 + threadIdx.x;   // (MM/4)*128
  int d4 = idx & 127, g = idx >> 7;         // g in [0, MM/4)
  int b = g >> 9, sg = g & 511;
  int m0 = b*Ss + sg*4;
  int d = d4*4;
  float4 w0 = *(const float4*)(cw + (d+0)*4);
  float4 w1 = *(const float4*)(cw + (d+1)*4);
  float4 w2 = *(const float4*)(cw + (d+2)*4);
  float4 w3 = *(const float4*)(cw + (d+3)*4);
  float4 bv = *(const float4*)(cb + d);
  float4 x0, x1, x2;
  if (sg > 0){
    x0 = *(const float4*)&g_xs[(m0-3)*DIi + d];
    x1 = *(const float4*)&g_xs[(m0-2)*DIi + d];
    x2 = *(const float4*)&g_xs[(m0-1)*DIi + d];
  } else {
    x0 = x1 = x2 = make_float4(0.f,0.f,0.f,0.f);
  }
  #pragma unroll
  for (int s=0;s<4;s++){
    float4 x3 = *(const float4*)&g_xs[(m0+s)*DIi + d];
    float4 a;
    a.x = bv.x + w0.x*x0.x + w0.y*x1.x + w0.z*x2.x + w0.w*x3.x;
    a.y = bv.y + w1.x*x0.y + w1.y*x1.y + w1.z*x2.y + w1.w*x3.y;
    a.z = bv.z + w2.x*x0.z + w2.y*x1.z + w2.z*x2.z + w2.w*x3.z;
    a.w = bv.w + w3.x*x0.w + w3.y*x1.w + w3.z*x2.w + w3.w*x3.w;
    a.x = siluf(a.x); a.y = siluf(a.y); a.z = siluf(a.z); a.w = siluf(a.w);
    *(float4*)&g_xc[(m0+s)*DIi + d] = a;
    x0 = x1; x1 = x2; x2 = x3;
  }
}

// dA helper: if A[n] == -(n+1) (the actual dataset), dA_n = r^(n+1) with
// r = exp(-delta): 1 MUFU + 15 FMUL (log depth) instead of 16 MUFU.
__device__ __forceinline__ void dA_compute(float* dAv, const float* A,
                                           float dlt, bool fast){
  if (fast){
    float r = __expf(-dlt);
    dAv[0] = r; dAv[1] = r*r;
    #pragma unroll
    for (int n=2;n<NN;n++) dAv[n] = dAv[n>>1]*dAv[(n-1)>>1];
  } else {
    #pragma unroll
    for (int n=0;n<NN;n++) dAv[n] = __expf(dlt*A[n]);
  }
}

__device__ __forceinline__ bool a_fast(const float* A){
  bool f = true;
  #pragma unroll
  for (int n=0;n<NN;n++) f = f && (fabsf(A[n] + (float)(n+1)) < 1e-5f*(n+1));
  return f;
}

// ---------------- chunked scan phase 1 (256 threads, half channels per block) ----------------
__global__ void k_scan1(const float* __restrict__ Alog){
  __shared__ float sB[CHUNK][NN];
  int blk = blockIdx.x;               // 2 * Bb*NCH
  int bc_ = blk >> 1;
  int b = bc_ >> 6, c = bc_ & 63;
  int d = (blk & 1)*256 + threadIdx.x;
  int m0 = b*Ss + c*CHUNK;
  { int i0 = threadIdx.x, i1 = threadIdx.x + 256;
    sB[i0>>4][i0&15] = g_proj[(m0+(i0>>4))*64 + 32 + (i0&15)];
    sB[i1>>4][i1&15] = g_proj[(m0+(i1>>4))*64 + 32 + (i1&15)]; }
  float A[NN];
  #pragma unroll
  for (int n=0;n<NN;n++) A[n] = -__expf(Alog[d*NN + n]);
  bool fast = a_fast(A);
  __syncthreads();
  float h[NN];
  #pragma unroll
  for (int n=0;n<NN;n++) h[n] = 0.f;
  float sd = 0.f;
  #pragma unroll 1
  for (int s=0;s<CHUNK;s++){
    int m = m0 + s;
    float dlt = g_delta[m*DIi + d];
    float dx  = dlt * g_xc[m*DIi + d];
    sd += dlt;
    float dAv[NN];
    dA_compute(dAv, A, dlt, fast);
    #pragma unroll
    for (int n=0;n<NN;n++) h[n] = dAv[n]*h[n] + dx*sB[s][n];
  }
  int base = (bc_*DIi + d)*NN;
  float Pv[NN];
  dA_compute(Pv, A, sd, fast);
  #pragma unroll
  for (int n=0;n<NN;n++){ g_Q[base+n]=h[n]; g_P[base+n]=Pv[n]; }
}

// ---------------- phase 2: combine across chunks ----------------
__global__ void k_comb(){
  int i = blockIdx.x*128 + threadIdx.x;     // Bb*DIi*NN = 16384
  int n = i & 15, d = (i >> 4) & (DIi-1), b = i >> 13;
  float H = 0.f;
  for (int c=0;c<NCH;c++){
    int idx = ((b*NCH+c)*DIi + d)*NN + n;
    g_Hin[idx] = H;
    H = g_P[idx]*H + g_Q[idx];
  }
}

// ---------------- phase 3: replay + gated output ----------------
__global__ void k_scan2(const float* __restrict__ Alog, const float* __restrict__ Dp){
  __shared__ float sB[CHUNK][NN];
  __shared__ float sC[CHUNK][NN];
  int blk = blockIdx.x;
  int bc_ = blk >> 1;
  int b = bc_ >> 6, c = bc_ & 63;
  int d = (blk & 1)*256 + threadIdx.x;
  int m0 = b*Ss + c*CHUNK;
  { int i0 = threadIdx.x, i1 = threadIdx.x + 256;
    sB[i0>>4][i0&15] = g_proj[(m0+(i0>>4))*64 + 32 + (i0&15)];
    sB[i1>>4][i1&15] = g_proj[(m0+(i1>>4))*64 + 32 + (i1&15)];
    sC[i0>>4][i0&15] = g_proj[(m0+(i0>>4))*64 + 48 + (i0&15)];
    sC[i1>>4][i1&15] = g_proj[(m0+(i1>>4))*64 + 48 + (i1&15)]; }
  float A[NN];
  #pragma unroll
  for (int n=0;n<NN;n++) A[n] = -__expf(Alog[d*NN + n]);
  bool fast = a_fast(A);
  float h[NN];
  int base = (bc_*DIi + d)*NN;
  #pragma unroll
  for (int n=0;n<NN;n++) h[n] = g_Hin[base+n];
  float Dv = Dp[d];
  __syncthreads();
  #pragma unroll 1
  for (int s=0;s<CHUNK;s++){
    int m = m0 + s;
    float dlt = g_delta[m*DIi + d];
    float x   = g_xc[m*DIi + d];
    float dx  = dlt * x;
    float dAv[NN];
    dA_compute(dAv, A, dlt, fast);
    float y = 0.f;
    #pragma unroll
    for (int n=0;n<NN;n++){
      h[n] = dAv[n]*h[n] + dx*sB[s][n];
      y += h[n]*sC[s][n];
    }
    y += Dv*x;
    float zv = g_z[m*DIi + d];
    g_yg[m*DIi + d] = y * siluf(zv);
  }
}

// ---------------- driver ----------------
extern "C" void kernel_launch(void* const* d_in, const int* in_sizes, int n_in,
                              void* d_out, int out_size){
  const float* x      = (const float*)d_in[0];
  const float* in_w   = (const float*)d_in[1];
  const float* conv_w = (const float*)d_in[2];
  const float* conv_b = (const float*)d_in[3];
  const float* A_log  = (const float*)d_in[4];
  const float* xd_w   = (const float*)d_in[5];
  const float* xB_w   = (const float*)d_in[6];
  const float* xC_w   = (const float*)d_in[7];
  const float* dtp_w  = (const float*)d_in[8];
  const float* dtp_b  = (const float*)d_in[9];
  const float* Dp     = (const float*)d_in[10];
  const float* out_w  = (const float*)d_in[11];
  const float* ln_g   = (const float*)d_in[12];
  const float* ln_b   = (const float*)d_in[13];
  const float* merge_w= (const float*)d_in[14];
  float* out = (float*)d_out;

  for (int chain=0; chain<2; chain++){
    k_init<<<MM*64/256, 256>>>(x, chain);
    for (int bi=0; bi<2; bi++){
      int blk = chain*2 + bi;
      k_ln      <<<MM/8, 256>>>(ln_g + blk*DMm, ln_b + blk*DMm);
      k_gemm_in <<<dim3(16,32), 256>>>(in_w + (size_t)blk*DMm*2*DIi);
      k_conv    <<<(MM/4)*128/256, 256>>>(conv_w + blk*DIi*4, conv_b + blk*DIi);
      k_gemm_x  <<<dim3(KS,32), 256>>>(xd_w + blk*DIi*RR,
                                       xB_w + blk*DIi*NN,
                                       xC_w + blk*DIi*NN);
      k_xred    <<<MM*16/256, 256>>>();
      k_gemm_dt <<<dim3(8,32), 256>>>(dtp_w + blk*RR*DIi, dtp_b + blk*DIi);
      k_scan1   <<<2*Bb*NCH, 256>>>(A_log + blk*DIi*NN);
      k_comb    <<<128, 128>>>();
      k_scan2   <<<2*Bb*NCH, 256>>>(A_log + blk*DIi*NN, Dp + blk*DIi);
      k_gemm_out<<<dim3(4,32), 256>>>(out_w + blk*DIi*DMm);
    }
    if (chain == 0) k_copy<<<MM*64/256, 256>>>();
  }
  k_merge<<<dim3(4,32), 256>>>(merge_w, out);
}

// round 6
// speedup vs baseline: 2.7575x; 1.0536x over previous
#include <cuda_runtime.h>
#include <cuda_fp16.h>

// ---------------- problem constants ----------------
#define Bb   2
#define Ss   2048
#define DMm  256
#define DIi  512
#define NN   16
#define RR   32
#define MM   (Bb*Ss)          // 4096 rows per chain
#define M2   (2*MM)           // 8192 rows: [fwd | reversed]
#define CHUNK 32
#define NCH  (Ss/CHUNK)       // 64 chunks per sequence
#define NSEQ 4                // 4 sequences total (2 fwd + 2 rev)
#define KS   4                // split-K for x-proj

// ---------------- device scratch ----------------
__device__ float g_res [M2*DMm];
__device__ float g_xs  [M2*DIi];
__device__ float g_z   [M2*DIi];
__device__ float g_xc  [M2*DIi];
__device__ float g_proj[M2*64];          // [xd(32) | B(16) | C(16)]
__device__ float g_projp[KS*M2*64];      // split-K partials
__device__ float g_delta[M2*DIi];
__device__ float g_yg  [M2*DIi];
__device__ float g_P   [NSEQ*NCH*DIi*NN];
__device__ float g_Q   [NSEQ*NCH*DIi*NN];
__device__ float g_Hin [NSEQ*NCH*DIi*NN];

__device__ __forceinline__ float siluf(float x){ return x / (1.f + __expf(-x)); }
__device__ __forceinline__ float spf(float a){ return (a > 20.f) ? a : log1pf(__expf(a)); }

__device__ __forceinline__ unsigned h2pack(float a, float b){
  __half2 h = __floats2half2_rn(a, b);
  return *reinterpret_cast<unsigned*>(&h);
}

#define MMA16(c, a, b)                                                       \
  asm volatile("mma.sync.aligned.m16n8k16.row.col.f32.f16.f16.f32 "          \
               "{%0,%1,%2,%3},{%4,%5,%6,%7},{%8,%9},{%0,%1,%2,%3};"          \
               : "+f"(c[0]), "+f"(c[1]), "+f"(c[2]), "+f"(c[3])              \
               : "r"(a[0]), "r"(a[1]), "r"(a[2]), "r"(a[3]),                 \
                 "r"(b[0]), "r"(b[1]))

// ---------------- init: fwd + reversed copies ----------------
__global__ void k_init(const float* __restrict__ x){
  int idx = blockIdx.x*256 + threadIdx.x;       // M2*64 float4s
  int col = idx & 63;
  int m   = idx >> 6;                           // 0..8191
  int half = m >> 12;
  int b = (m >> 11) & 1, s = m & (Ss-1);
  int ms = b*Ss + (half ? (Ss-1-s) : s);
  reinterpret_cast<float4*>(g_res)[m*64+col] =
      reinterpret_cast<const float4*>(x)[ms*64+col];
}

// ======================================================================
// FP16 tensor-core GEMM core, double-buffered, mma.m16n8k16.
// Block tile 128(M) x 64(N), 256 threads = 8 warps (4 M x 2 N),
// warp tile 32x32 = 2 mt x 4 nt. K-chunk = 16 = one mma k-step.
// Fragments stored per-lane contiguous -> LDS.128/LDS.64 conflict-free.
// ======================================================================
#define TC_DECL()                                                     \
  __shared__ __align__(16) unsigned Af[2][1024];                      \
  __shared__ __align__(16) unsigned Bf[2][512];                       \
  const int t = threadIdx.x;                                          \
  const int lane = t & 31, wid = t >> 5;                              \
  const int wm = wid >> 1, wn = wid & 1;                              \
  const int s_r  = t >> 1;          /* A staging row 0..127  */       \
  const int s_kb = (t & 1) * 8;     /* A staging k base 0/8  */       \
  const int s_bq = t >> 6;          /* B staging k-quad 0..3 */       \
  const int s_bn = t & 63;          /* B staging n 0..63     */       \
  float acc[2][4][4] = {};                                            \
  float4 raA0, raA1;                                                  \
  float rb0, rb1, rb2, rb3;

#define TC_STAGE(buf) {                                               \
  int mt_ = s_r >> 4, rr_ = s_r & 15;                                 \
  int lb_ = (rr_ & 7) * 4;                                            \
  int rg_ = (rr_ >> 3) + ((s_kb >> 2) & 2);                           \
  unsigned* ab = &Af[buf][(mt_*32 + lb_)*4 + rg_];                    \
  ab[0]  = h2pack(raA0.x, raA0.y);                                    \
  ab[4]  = h2pack(raA0.z, raA0.w);                                    \
  ab[8]  = h2pack(raA1.x, raA1.y);                                    \
  ab[12] = h2pack(raA1.z, raA1.w);                                    \
  { int ln0 = (s_bn & 7)*4 + ((2*s_bq) & 3);                          \
    int rgB = s_bq >> 1;                                              \
    unsigned* bb = &Bf[buf][((s_bn >> 3)*32 + ln0)*2 + rgB];          \
    bb[0] = h2pack(rb0, rb1);                                         \
    bb[2] = h2pack(rb2, rb3); } }

#define TC_COMP(buf) {                                                \
  unsigned a_[2][4]; unsigned b_[4][2];                               \
  _Pragma("unroll") for (int mt=0;mt<2;mt++)                          \
    *(uint4*)a_[mt] = *(const uint4*)&Af[buf][((wm*2+mt)*32 + lane)*4]; \
  _Pragma("unroll") for (int nt=0;nt<4;nt++)                          \
    *(uint2*)b_[nt] = *(const uint2*)&Bf[buf][((wn*4+nt)*32 + lane)*2]; \
  _Pragma("unroll") for (int mt=0;mt<2;mt++)                          \
    _Pragma("unroll") for (int nt=0;nt<4;nt++)                        \
      MMA16(acc[mt][nt], a_[mt], b_[nt]); }

#define TC_BODY(KT)                                                   \
  LOADA(0); LOADB(0);                                                 \
  TC_STAGE(0);                                                        \
  if (16 < (KT)) { LOADA(16); LOADB(16); }                            \
  __syncthreads();                                                    \
  { int cur = 0;                                                      \
    _Pragma("unroll 1")                                               \
    for (int k0=0; k0<(KT); k0+=16){                                  \
      if (k0+16 < (KT)) TC_STAGE(cur^1);                              \
      if (k0+32 < (KT)) { LOADA(k0+32); LOADB(k0+32); }               \
      TC_COMP(cur);                                                   \
      __syncthreads();                                                \
      cur ^= 1;                                                       \
    } }

// in_proj with fused LayerNorm:
//   LN(g_res)[8192,256] @ in_w[256,1024] -> xs | z   (per-half weights)
__global__ void k_gemm_in(const float* __restrict__ W0, const float* __restrict__ W1,
                          const float* __restrict__ g0, const float* __restrict__ bt0,
                          const float* __restrict__ g1, const float* __restrict__ bt1){
  int col0 = blockIdx.x*64, row0 = blockIdx.y*128;
  int half = row0 >> 12;
  const float* W  = half ? W1  : W0;
  const float* gm = half ? g1  : g0;
  const float* bb = half ? bt1 : bt0;
  __shared__ float sG[DMm], sBt[DMm];
  TC_DECL();
  sG[t] = gm[t]; sBt[t] = bb[t];
  // per-row LN stats: thread covers k = {16j + s_kb .. +7}; partner (t^1) rest
  const float* rowp = g_res + (size_t)(row0 + s_r)*DMm;
  float sum = 0.f, sq = 0.f;
  #pragma unroll
  for (int j=0;j<16;j++){
    float4 v0 = *(const float4*)&rowp[j*16 + s_kb];
    float4 v1 = *(const float4*)&rowp[j*16 + s_kb + 4];
    sum += v0.x+v0.y+v0.z+v0.w + v1.x+v1.y+v1.z+v1.w;
    sq  += v0.x*v0.x+v0.y*v0.y+v0.z*v0.z+v0.w*v0.w
         + v1.x*v1.x+v1.y*v1.y+v1.z*v1.z+v1.w*v1.w;
  }
  sum += __shfl_xor_sync(~0u, sum, 1);
  sq  += __shfl_xor_sync(~0u, sq, 1);
  float mean = sum*(1.f/DMm);
  float rstd = rsqrtf(sq*(1.f/DMm) - mean*mean + 1e-5f);
  __syncthreads();   // sG/sBt visible before LOADA transforms
#define LOADA(k0_) { int kk_=(k0_)+s_kb;                                           \
    raA0 = *(const float4*)&rowp[kk_];                                             \
    raA1 = *(const float4*)&rowp[kk_+4];                                           \
    raA0.x=(raA0.x-mean)*rstd*sG[kk_+0]+sBt[kk_+0];                                \
    raA0.y=(raA0.y-mean)*rstd*sG[kk_+1]+sBt[kk_+1];                                \
    raA0.z=(raA0.z-mean)*rstd*sG[kk_+2]+sBt[kk_+2];                                \
    raA0.w=(raA0.w-mean)*rstd*sG[kk_+3]+sBt[kk_+3];                                \
    raA1.x=(raA1.x-mean)*rstd*sG[kk_+4]+sBt[kk_+4];                                \
    raA1.y=(raA1.y-mean)*rstd*sG[kk_+5]+sBt[kk_+5];                                \
    raA1.z=(raA1.z-mean)*rstd*sG[kk_+6]+sBt[kk_+6];                                \
    raA1.w=(raA1.w-mean)*rstd*sG[kk_+7]+sBt[kk_+7]; }
#define LOADB(k0_) { int kb_ = (k0_) + s_bq*4;                                     \
                     rb0 = W[(size_t)(kb_+0)*(2*DIi) + col0 + s_bn];               \
                     rb1 = W[(size_t)(kb_+1)*(2*DIi) + col0 + s_bn];               \
                     rb2 = W[(size_t)(kb_+2)*(2*DIi) + col0 + s_bn];               \
                     rb3 = W[(size_t)(kb_+3)*(2*DIi) + col0 + s_bn]; }
  TC_BODY(DMm);
#undef LOADA
#undef LOADB
  float* dst = (col0 < DIi) ? g_xs : g_z;
  int cb = (col0 < DIi) ? col0 : col0 - DIi;
  #pragma unroll
  for (int mt=0;mt<2;mt++)
    #pragma unroll
    for (int nt=0;nt<4;nt++){
      int r = row0 + wm*32 + mt*16 + (lane>>2);
      int c = cb + wn*32 + nt*8 + (lane&3)*2;
      *(float2*)&dst[(size_t)r*DIi + c]     = make_float2(acc[mt][nt][0], acc[mt][nt][1]);
      *(float2*)&dst[(size_t)(r+8)*DIi + c] = make_float2(acc[mt][nt][2], acc[mt][nt][3]);
    }
}

// x-proj split-K: xc[8192,512] @ [xd(32)|xB(16)|xC(16)] -> projp[kz]
__global__ void k_gemm_x(const float* __restrict__ xdw0, const float* __restrict__ xbw0,
                         const float* __restrict__ xcw0,
                         const float* __restrict__ xdw1, const float* __restrict__ xbw1,
                         const float* __restrict__ xcw1){
  int kz = blockIdx.x, row0 = blockIdx.y*128;
  int half = row0 >> 12;
  int kbase = kz*(DIi/KS);
  TC_DECL();
  const float* bsrc; int ldb, boff;
  if      (s_bn < 32){ bsrc = half?xdw1:xdw0; ldb = 32; boff = s_bn;      }
  else if (s_bn < 48){ bsrc = half?xbw1:xbw0; ldb = 16; boff = s_bn - 32; }
  else               { bsrc = half?xcw1:xcw0; ldb = 16; boff = s_bn - 48; }
#define LOADA(k0_) { raA0 = *(const float4*)&g_xc[(size_t)(row0+s_r)*DIi + kbase+(k0_)+s_kb];    \
                     raA1 = *(const float4*)&g_xc[(size_t)(row0+s_r)*DIi + kbase+(k0_)+s_kb+4]; }
#define LOADB(k0_) { int kb_ = kbase + (k0_) + s_bq*4;                                   \
                     rb0 = bsrc[(kb_+0)*ldb + boff];                                     \
                     rb1 = bsrc[(kb_+1)*ldb + boff];                                     \
                     rb2 = bsrc[(kb_+2)*ldb + boff];                                     \
                     rb3 = bsrc[(kb_+3)*ldb + boff]; }
  TC_BODY(DIi/KS);
#undef LOADA
#undef LOADB
  float* dst = g_projp + (size_t)kz*M2*64;
  #pragma unroll
  for (int mt=0;mt<2;mt++)
    #pragma unroll
    for (int nt=0;nt<4;nt++){
      int r = row0 + wm*32 + mt*16 + (lane>>2);
      int c = wn*32 + nt*8 + (lane&3)*2;
      *(float2*)&dst[(size_t)r*64 + c]     = make_float2(acc[mt][nt][0], acc[mt][nt][1]);
      *(float2*)&dst[(size_t)(r+8)*64 + c] = make_float2(acc[mt][nt][2], acc[mt][nt][3]);
    }
}

__global__ void k_xred(){
  int i = blockIdx.x*256 + threadIdx.x;   // M2*16 float4s
  float4 a = reinterpret_cast<const float4*>(g_projp)[i];
  float4 b = reinterpret_cast<const float4*>(g_projp + (size_t)M2*64)[i];
  float4 c = reinterpret_cast<const float4*>(g_projp + (size_t)2*M2*64)[i];
  float4 d = reinterpret_cast<const float4*>(g_projp + (size_t)3*M2*64)[i];
  reinterpret_cast<float4*>(g_proj)[i] =
      make_float4(a.x+b.x+c.x+d.x, a.y+b.y+c.y+d.y,
                  a.z+b.z+c.z+d.z, a.w+b.w+c.w+d.w);
}

// delta: softplus(proj[:, :32] @ dtp_w[32,512] + dtp_b) -> g_delta
__global__ void k_gemm_dt(const float* __restrict__ Wd0, const float* __restrict__ bd0,
                          const float* __restrict__ Wd1, const float* __restrict__ bd1){
  int col0 = blockIdx.x*64, row0 = blockIdx.y*128;
  int half = row0 >> 12;
  const float* Wd = half ? Wd1 : Wd0;
  const float* bd = half ? bd1 : bd0;
  TC_DECL();
#define LOADA(k0_) { raA0 = *(const float4*)&g_proj[(size_t)(row0+s_r)*64 + (k0_)+s_kb];    \
                     raA1 = *(const float4*)&g_proj[(size_t)(row0+s_r)*64 + (k0_)+s_kb+4]; }
#define LOADB(k0_) { int kb_ = (k0_) + s_bq*4;                                      \
                     rb0 = Wd[(kb_+0)*DIi + col0 + s_bn];                           \
                     rb1 = Wd[(kb_+1)*DIi + col0 + s_bn];                           \
                     rb2 = Wd[(kb_+2)*DIi + col0 + s_bn];                           \
                     rb3 = Wd[(kb_+3)*DIi + col0 + s_bn]; }
  TC_BODY(RR);
#undef LOADA
#undef LOADB
  #pragma unroll
  for (int mt=0;mt<2;mt++)
    #pragma unroll
    for (int nt=0;nt<4;nt++){
      int r = row0 + wm*32 + mt*16 + (lane>>2);
      int c = col0 + wn*32 + nt*8 + (lane&3)*2;
      float b0 = bd[c], b1 = bd[c+1];
      *(float2*)&g_delta[(size_t)r*DIi + c] =
          make_float2(spf(acc[mt][nt][0]+b0), spf(acc[mt][nt][1]+b1));
      *(float2*)&g_delta[(size_t)(r+8)*DIi + c] =
          make_float2(spf(acc[mt][nt][2]+b0), spf(acc[mt][nt][3]+b1));
    }
}

// out_proj: yg[8192,512] @ out_w[512,256] + residual (in place on g_res)
__global__ void k_gemm_out(const float* __restrict__ W0, const float* __restrict__ W1){
  int col0 = blockIdx.x*64, row0 = blockIdx.y*128;
  int half = row0 >> 12;
  const float* W = half ? W1 : W0;
  TC_DECL();
#define LOADA(k0_) { raA0 = *(const float4*)&g_yg[(size_t)(row0+s_r)*DIi + (k0_)+s_kb];    \
                     raA1 = *(const float4*)&g_yg[(size_t)(row0+s_r)*DIi + (k0_)+s_kb+4]; }
#define LOADB(k0_) { int kb_ = (k0_) + s_bq*4;                                     \
                     rb0 = W[(kb_+0)*DMm + col0 + s_bn];                           \
                     rb1 = W[(kb_+1)*DMm + col0 + s_bn];                           \
                     rb2 = W[(kb_+2)*DMm + col0 + s_bn];                           \
                     rb3 = W[(kb_+3)*DMm + col0 + s_bn]; }
  TC_BODY(DIi);
#undef LOADA
#undef LOADB
  #pragma unroll
  for (int mt=0;mt<2;mt++)
    #pragma unroll
    for (int nt=0;nt<4;nt++){
      int r = row0 + wm*32 + mt*16 + (lane>>2);
      int c = col0 + wn*32 + nt*8 + (lane&3)*2;
      float2 o0 = *(const float2*)&g_res[(size_t)r*DMm + c];
      float2 o1 = *(const float2*)&g_res[(size_t)(r+8)*DMm + c];
      *(float2*)&g_res[(size_t)r*DMm + c] =
          make_float2(acc[mt][nt][0]+o0.x, acc[mt][nt][1]+o0.y);
      *(float2*)&g_res[(size_t)(r+8)*DMm + c] =
          make_float2(acc[mt][nt][2]+o1.x, acc[mt][nt][3]+o1.y);
    }
}

// merge: concat(res_half0, res_half1_reversed)[4096,512] @ merge_w[512,256] -> out
__global__ void k_merge(const float* __restrict__ W, float* __restrict__ out){
  int col0 = blockIdx.x*64, row0 = blockIdx.y*128;
  TC_DECL();
  int r_ = row0 + s_r;                 // 0..4095
  int b_ = r_ >> 11, s_ = r_ & (Ss-1);
  int rrev = MM + b_*Ss + (Ss-1-s_);   // reversed row in half 1
#define LOADA(k0_) {                                                               \
    int kk0 = (k0_)+s_kb, kk1 = (k0_)+s_kb+4;                                      \
    raA0 = *(const float4*)((kk0 < DMm) ? (g_res + (size_t)r_*DMm + kk0)           \
                                        : (g_res + (size_t)rrev*DMm + kk0-DMm));   \
    raA1 = *(const float4*)((kk1 < DMm) ? (g_res + (size_t)r_*DMm + kk1)           \
                                        : (g_res + (size_t)rrev*DMm + kk1-DMm)); }
#define LOADB(k0_) { int kb_ = (k0_) + s_bq*4;                                     \
                     rb0 = W[(kb_+0)*DMm + col0 + s_bn];                           \
                     rb1 = W[(kb_+1)*DMm + col0 + s_bn];                           \
                     rb2 = W[(kb_+2)*DMm + col0 + s_bn];                           \
                     rb3 = W[(kb_+3)*DMm + col0 + s_bn]; }
  TC_BODY(2*DMm);
#undef LOADA
#undef LOADB
  #pragma unroll
  for (int mt=0;mt<2;mt++)
    #pragma unroll
    for (int nt=0;nt<4;nt++){
      int r = row0 + wm*32 + mt*16 + (lane>>2);
      int c = col0 + wn*32 + nt*8 + (lane&3)*2;
      *(float2*)&out[(size_t)r*DMm + c]     = make_float2(acc[mt][nt][0], acc[mt][nt][1]);
      *(float2*)&out[(size_t)(r+8)*DMm + c] = make_float2(acc[mt][nt][2], acc[mt][nt][3]);
    }
}

// ---------------- causal depthwise conv (K=4) + silu, 4 s-positions/thread ----------------
__global__ void k_conv(const float* __restrict__ cw0, const float* __restrict__ cb0,
                       const float* __restrict__ cw1, const float* __restrict__ cb1){
  int idx = blockIdx.x*256 + threadIdx.x;   // (M2/4)*128
  int d4 = idx & 127, g = idx >> 7;         // g in [0, M2/4)
  int b2 = g >> 9, sg = g & 511;            // seq 0..3, group within seq
  int half = b2 >> 1;
  const float* cw = half ? cw1 : cw0;
  const float* cb = half ? cb1 : cb0;
  int m0 = b2*Ss + sg*4;
  int d = d4*4;
  float4 w0 = *(const float4*)(cw + (d+0)*4);
  float4 w1 = *(const float4*)(cw + (d+1)*4);
  float4 w2 = *(const float4*)(cw + (d+2)*4);
  float4 w3 = *(const float4*)(cw + (d+3)*4);
  float4 bv = *(const float4*)(cb + d);
  float4 x0, x1, x2;
  if (sg > 0){
    x0 = *(const float4*)&g_xs[(size_t)(m0-3)*DIi + d];
    x1 = *(const float4*)&g_xs[(size_t)(m0-2)*DIi + d];
    x2 = *(const float4*)&g_xs[(size_t)(m0-1)*DIi + d];
  } else {
    x0 = x1 = x2 = make_float4(0.f,0.f,0.f,0.f);
  }
  #pragma unroll
  for (int s=0;s<4;s++){
    float4 x3 = *(const float4*)&g_xs[(size_t)(m0+s)*DIi + d];
    float4 a;
    a.x = bv.x + w0.x*x0.x + w0.y*x1.x + w0.z*x2.x + w0.w*x3.x;
    a.y = bv.y + w1.x*x0.y + w1.y*x1.y + w1.z*x2.y + w1.w*x3.y;
    a.z = bv.z + w2.x*x0.z + w2.y*x1.z + w2.z*x2.z + w2.w*x3.z;
    a.w = bv.w + w3.x*x0.w + w3.y*x1.w + w3.z*x2.w + w3.w*x3.w;
    a.x = siluf(a.x); a.y = siluf(a.y); a.z = siluf(a.z); a.w = siluf(a.w);
    *(float4*)&g_xc[(size_t)(m0+s)*DIi + d] = a;
    x0 = x1; x1 = x2; x2 = x3;
  }
}

// dA helper: if A[n] == -(n+1) (the actual dataset), dA_n = r^(n+1) with
// r = exp(-delta): 1 MUFU + 15 FMUL instead of 16 MUFU.
__device__ __forceinline__ void dA_compute(float* dAv, const float* A,
                                           float dlt, bool fast){
  if (fast){
    float r = __expf(-dlt);
    dAv[0] = r; dAv[1] = r*r;
    #pragma unroll
    for (int n=2;n<NN;n++) dAv[n] = dAv[n>>1]*dAv[(n-1)>>1];
  } else {
    #pragma unroll
    for (int n=0;n<NN;n++) dAv[n] = __expf(dlt*A[n]);
  }
}

__device__ __forceinline__ bool a_fast(const float* A){
  bool f = true;
  #pragma unroll
  for (int n=0;n<NN;n++) f = f && (fabsf(A[n] + (float)(n+1)) < 1e-5f*(n+1));
  return f;
}

// ---------------- chunked scan phase 1 ----------------
__global__ void k_scan1(const float* __restrict__ Alog0, const float* __restrict__ Alog1){
  __shared__ float sB[CHUNK][NN];
  int blk = blockIdx.x;               // 2 * NSEQ*NCH = 512
  int bc_ = blk >> 1;                 // 0..255
  int seq = bc_ >> 6, c = bc_ & 63;
  int half = seq >> 1;
  const float* Alog = half ? Alog1 : Alog0;
  int d = (blk & 1)*256 + threadIdx.x;
  int m0 = seq*Ss + c*CHUNK;
  { int i0 = threadIdx.x, i1 = threadIdx.x + 256;
    sB[i0>>4][i0&15] = g_proj[(size_t)(m0+(i0>>4))*64 + 32 + (i0&15)];
    sB[i1>>4][i1&15] = g_proj[(size_t)(m0+(i1>>4))*64 + 32 + (i1&15)]; }
  float A[NN];
  #pragma unroll
  for (int n=0;n<NN;n++) A[n] = -__expf(Alog[d*NN + n]);
  bool fast = a_fast(A);
  __syncthreads();
  float h[NN];
  #pragma unroll
  for (int n=0;n<NN;n++) h[n] = 0.f;
  float sd = 0.f;
  #pragma unroll 1
  for (int s=0;s<CHUNK;s++){
    size_t m = m0 + s;
    float dlt = g_delta[m*DIi + d];
    float dx  = dlt * g_xc[m*DIi + d];
    sd += dlt;
    float dAv[NN];
    dA_compute(dAv, A, dlt, fast);
    #pragma unroll
    for (int n=0;n<NN;n++) h[n] = dAv[n]*h[n] + dx*sB[s][n];
  }
  size_t base = ((size_t)bc_*DIi + d)*NN;
  float Pv[NN];
  dA_compute(Pv, A, sd, fast);
  #pragma unroll
  for (int n=0;n<NN;n++){ g_Q[base+n]=h[n]; g_P[base+n]=Pv[n]; }
}

// ---------------- phase 2: combine across chunks ----------------
__global__ void k_comb(){
  int i = blockIdx.x*128 + threadIdx.x;     // NSEQ*DIi*NN = 32768
  int n = i & 15, d = (i >> 4) & (DIi-1), seq = i >> 13;
  float H = 0.f;
  for (int c=0;c<NCH;c++){
    size_t idx = (((size_t)(seq*NCH+c))*DIi + d)*NN + n;
    g_Hin[idx] = H;
    H = g_P[idx]*H + g_Q[idx];
  }
}

// ---------------- phase 3: replay + gated output ----------------
__global__ void k_scan2(const float* __restrict__ Alog0, const float* __restrict__ Alog1,
                        const float* __restrict__ Dp0, const float* __restrict__ Dp1){
  __shared__ float sB[CHUNK][NN];
  __shared__ float sC[CHUNK][NN];
  int blk = blockIdx.x;
  int bc_ = blk >> 1;
  int seq = bc_ >> 6, c = bc_ & 63;
  int half = seq >> 1;
  const float* Alog = half ? Alog1 : Alog0;
  const float* Dp   = half ? Dp1   : Dp0;
  int d = (blk & 1)*256 + threadIdx.x;
  int m0 = seq*Ss + c*CHUNK;
  { int i0 = threadIdx.x, i1 = threadIdx.x + 256;
    sB[i0>>4][i0&15] = g_proj[(size_t)(m0+(i0>>4))*64 + 32 + (i0&15)];
    sB[i1>>4][i1&15] = g_proj[(size_t)(m0+(i1>>4))*64 + 32 + (i1&15)];
    sC[i0>>4][i0&15] = g_proj[(size_t)(m0+(i0>>4))*64 + 48 + (i0&15)];
    sC[i1>>4][i1&15] = g_proj[(size_t)(m0+(i1>>4))*64 + 48 + (i1&15)]; }
  float A[NN];
  #pragma unroll
  for (int n=0;n<NN;n++) A[n] = -__expf(Alog[d*NN + n]);
  bool fast = a_fast(A);
  float h[NN];
  size_t base = ((size_t)bc_*DIi + d)*NN;
  #pragma unroll
  for (int n=0;n<NN;n++) h[n] = g_Hin[base+n];
  float Dv = Dp[d];
  __syncthreads();
  #pragma unroll 1
  for (int s=0;s<CHUNK;s++){
    size_t m = m0 + s;
    float dlt = g_delta[m*DIi + d];
    float x   = g_xc[m*DIi + d];
    float dx  = dlt * x;
    float dAv[NN];
    dA_compute(dAv, A, dlt, fast);
    float y = 0.f;
    #pragma unroll
    for (int n=0;n<NN;n++){
      h[n] = dAv[n]*h[n] + dx*sB[s][n];
      y += h[n]*sC[s][n];
    }
    y += Dv*x;
    float zv = g_z[m*DIi + d];
    g_yg[m*DIi + d] = y * siluf(zv);
  }
}

// ---------------- driver ----------------
extern "C" void kernel_launch(void* const* d_in, const int* in_sizes, int n_in,
                              void* d_out, int out_size){
  const float* x      = (const float*)d_in[0];
  const float* in_w   = (const float*)d_in[1];
  const float* conv_w = (const float*)d_in[2];
  const float* conv_b = (const float*)d_in[3];
  const float* A_log  = (const float*)d_in[4];
  const float* xd_w   = (const float*)d_in[5];
  const float* xB_w   = (const float*)d_in[6];
  const float* xC_w   = (const float*)d_in[7];
  const float* dtp_w  = (const float*)d_in[8];
  const float* dtp_b  = (const float*)d_in[9];
  const float* Dp     = (const float*)d_in[10];
  const float* out_w  = (const float*)d_in[11];
  const float* ln_g   = (const float*)d_in[12];
  const float* ln_b   = (const float*)d_in[13];
  const float* merge_w= (const float*)d_in[14];
  float* out = (float*)d_out;

  k_init<<<M2*64/256, 256>>>(x);
  for (int bi=0; bi<2; bi++){
    int b0 = bi, b1 = 2 + bi;
    k_gemm_in <<<dim3(16,64), 256>>>(in_w + (size_t)b0*DMm*2*DIi,
                                     in_w + (size_t)b1*DMm*2*DIi,
                                     ln_g + b0*DMm, ln_b + b0*DMm,
                                     ln_g + b1*DMm, ln_b + b1*DMm);
    k_conv    <<<(M2/4)*128/256, 256>>>(conv_w + b0*DIi*4, conv_b + b0*DIi,
                                        conv_w + b1*DIi*4, conv_b + b1*DIi);
    k_gemm_x  <<<dim3(KS,64), 256>>>(xd_w + b0*DIi*RR, xB_w + b0*DIi*NN, xC_w + b0*DIi*NN,
                                     xd_w + b1*DIi*RR, xB_w + b1*DIi*NN, xC_w + b1*DIi*NN);
    k_xred    <<<M2*16/256, 256>>>();
    k_gemm_dt <<<dim3(8,64), 256>>>(dtp_w + b0*RR*DIi, dtp_b + b0*DIi,
                                    dtp_w + b1*RR*DIi, dtp_b + b1*DIi);
    k_scan1   <<<2*NSEQ*NCH, 256>>>(A_log + b0*DIi*NN, A_log + b1*DIi*NN);
    k_comb    <<<256, 128>>>();
    k_scan2   <<<2*NSEQ*NCH, 256>>>(A_log + b0*DIi*NN, A_log + b1*DIi*NN,
                                    Dp + b0*DIi, Dp + b1*DIi);
    k_gemm_out<<<dim3(4,64), 256>>>(out_w + (size_t)b0*DIi*DMm,
                                    out_w + (size_t)b1*DIi*DMm);
  }
  k_merge<<<dim3(4,32), 256>>>(merge_w, out);
}

// round 7
// speedup vs baseline: 2.9597x; 1.0733x over previous
#include <cuda_runtime.h>
#include <cuda_fp16.h>

// ---------------- problem constants ----------------
#define Bb   2
#define Ss   2048
#define DMm  256
#define DIi  512
#define NN   16
#define RR   32
#define MM   (Bb*Ss)          // 4096 rows per chain
#define M2   (2*MM)           // 8192 rows: [fwd | reversed]
#define CHUNK 32
#define NCH  (Ss/CHUNK)       // 64 chunks per sequence
#define NSEQ 4                // 4 sequences total (2 fwd + 2 rev)
#define KS   4                // split-K for x-proj

// ---------------- device scratch ----------------
__device__ float  g_res [M2*DMm];
__device__ __half g_xs  [M2*DIi];
__device__ __half g_z   [M2*DIi];
__device__ __half g_xc  [M2*DIi];
__device__ float  g_proj[M2*64];          // [xd(32) | B(16) | C(16)] fp32
__device__ __half g_projh[M2*64];         // half mirror for gemm_dt A-path
__device__ float  g_projp[KS*M2*64];      // split-K partials (fp32)
__device__ __half g_delta[M2*DIi];
__device__ __half g_yg  [M2*DIi];
__device__ float  g_P   [NSEQ*NCH*DIi*NN];
__device__ float  g_Q   [NSEQ*NCH*DIi*NN];
__device__ float  g_Hin [NSEQ*NCH*DIi*NN];

__device__ __forceinline__ float siluf(float x){ return x / (1.f + __expf(-x)); }
__device__ __forceinline__ float spf(float a){ return (a > 20.f) ? a : log1pf(__expf(a)); }

__device__ __forceinline__ unsigned h2pack(float a, float b){
  __half2 h = __floats2half2_rn(a, b);
  return *reinterpret_cast<unsigned*>(&h);
}
__device__ __forceinline__ float4 h4load(const __half* p){
  uint2 u = *(const uint2*)p;
  float2 fa = __half22float2(*(__half2*)&u.x);
  float2 fb = __half22float2(*(__half2*)&u.y);
  return make_float4(fa.x, fa.y, fb.x, fb.y);
}
__device__ __forceinline__ void h4store(__half* p, float4 v){
  uint2 u; u.x = h2pack(v.x, v.y); u.y = h2pack(v.z, v.w);
  *(uint2*)p = u;
}

#define MMA16(c, a, b)                                                       \
  asm volatile("mma.sync.aligned.m16n8k16.row.col.f32.f16.f16.f32 "          \
               "{%0,%1,%2,%3},{%4,%5,%6,%7},{%8,%9},{%0,%1,%2,%3};"          \
               : "+f"(c[0]), "+f"(c[1]), "+f"(c[2]), "+f"(c[3])              \
               : "r"(a[0]), "r"(a[1]), "r"(a[2]), "r"(a[3]),                 \
                 "r"(b[0]), "r"(b[1]))

// ---------------- init: fwd + reversed copies ----------------
__global__ void k_init(const float* __restrict__ x){
  int idx = blockIdx.x*256 + threadIdx.x;       // M2*64 float4s
  int col = idx & 63;
  int m   = idx >> 6;                           // 0..8191
  int half = m >> 12;
  int b = (m >> 11) & 1, s = m & (Ss-1);
  int ms = b*Ss + (half ? (Ss-1-s) : s);
  reinterpret_cast<float4*>(g_res)[m*64+col] =
      reinterpret_cast<const float4*>(x)[ms*64+col];
}

// ======================================================================
// FP16 tensor-core GEMM core, double-buffered, mma.m16n8k16.
// Block tile 128(M) x 64(N), 256 threads = 8 warps (4 M x 2 N).
// Fragments per-lane contiguous -> LDS.128/LDS.64 conflict-free.
// A-staging variants: _F converts fp32 regs, _H stores packed halves direct.
// ======================================================================
#define TC_DECL()                                                     \
  __shared__ __align__(16) unsigned Af[2][1024];                      \
  __shared__ __align__(16) unsigned Bf[2][512];                       \
  const int t = threadIdx.x;                                          \
  const int lane = t & 31, wid = t >> 5;                              \
  const int wm = wid >> 1, wn = wid & 1;                              \
  const int s_r  = t >> 1;          /* A staging row 0..127  */       \
  const int s_kb = (t & 1) * 8;     /* A staging k base 0/8  */       \
  const int s_bq = t >> 6;          /* B staging k-quad 0..3 */       \
  const int s_bn = t & 63;          /* B staging n 0..63     */       \
  float acc[2][4][4] = {};                                            \
  float4 raA0, raA1; uint4 raH;                                       \
  float rb0, rb1, rb2, rb3;                                           \
  (void)raA0; (void)raA1; (void)raH;

#define TC_AB(buf) &Af[buf][(((s_r>>4)*32 + ((s_r&7)*4))*4) + ((s_r>>3)&1) + ((s_kb>>2)&2)]

#define TC_STAGE_B(buf) {                                             \
  int ln0 = (s_bn & 7)*4 + ((2*s_bq) & 3);                            \
  int rgB = s_bq >> 1;                                                \
  unsigned* bb = &Bf[buf][((s_bn >> 3)*32 + ln0)*2 + rgB];            \
  bb[0] = h2pack(rb0, rb1);                                           \
  bb[2] = h2pack(rb2, rb3); }

#define TC_STAGE_F(buf) {                                             \
  unsigned* ab = TC_AB(buf);                                          \
  ab[0]  = h2pack(raA0.x, raA0.y);                                    \
  ab[4]  = h2pack(raA0.z, raA0.w);                                    \
  ab[8]  = h2pack(raA1.x, raA1.y);                                    \
  ab[12] = h2pack(raA1.z, raA1.w);                                    \
  TC_STAGE_B(buf) }

#define TC_STAGE_H(buf) {                                             \
  unsigned* ab = TC_AB(buf);                                          \
  ab[0]  = raH.x;                                                     \
  ab[4]  = raH.y;                                                     \
  ab[8]  = raH.z;                                                     \
  ab[12] = raH.w;                                                     \
  TC_STAGE_B(buf) }

#define TC_COMP(buf) {                                                \
  unsigned a_[2][4]; unsigned b_[4][2];                               \
  _Pragma("unroll") for (int mt=0;mt<2;mt++)                          \
    *(uint4*)a_[mt] = *(const uint4*)&Af[buf][((wm*2+mt)*32 + lane)*4]; \
  _Pragma("unroll") for (int nt=0;nt<4;nt++)                          \
    *(uint2*)b_[nt] = *(const uint2*)&Bf[buf][((wn*4+nt)*32 + lane)*2]; \
  _Pragma("unroll") for (int mt=0;mt<2;mt++)                          \
    _Pragma("unroll") for (int nt=0;nt<4;nt++)                        \
      MMA16(acc[mt][nt], a_[mt], b_[nt]); }

#define TC_BODY_GEN(KT, STG)                                          \
  LOADA(0); LOADB(0);                                                 \
  STG(0);                                                             \
  if (16 < (KT)) { LOADA(16); LOADB(16); }                            \
  __syncthreads();                                                    \
  { int cur = 0;                                                      \
    _Pragma("unroll 1")                                               \
    for (int k0=0; k0<(KT); k0+=16){                                  \
      if (k0+16 < (KT)) STG(cur^1);                                   \
      if (k0+32 < (KT)) { LOADA(k0+32); LOADB(k0+32); }               \
      TC_COMP(cur);                                                   \
      __syncthreads();                                                \
      cur ^= 1;                                                       \
    } }

#define TC_BODY(KT)   TC_BODY_GEN(KT, TC_STAGE_F)
#define TC_BODY_H(KT) TC_BODY_GEN(KT, TC_STAGE_H)

// in_proj with fused LayerNorm:
//   LN(g_res)[8192,256] @ in_w[256,1024] -> xs | z (half)   per-half weights
__global__ void k_gemm_in(const float* __restrict__ W0, const float* __restrict__ W1,
                          const float* __restrict__ g0, const float* __restrict__ bt0,
                          const float* __restrict__ g1, const float* __restrict__ bt1){
  int col0 = blockIdx.x*64, row0 = blockIdx.y*128;
  int half = row0 >> 12;
  const float* W  = half ? W1  : W0;
  const float* gm = half ? g1  : g0;
  const float* bb = half ? bt1 : bt0;
  __shared__ float sG[DMm], sBt[DMm];
  TC_DECL();
  sG[t] = gm[t]; sBt[t] = bb[t];
  const float* rowp = g_res + (size_t)(row0 + s_r)*DMm;
  float sum = 0.f, sq = 0.f;
  #pragma unroll
  for (int j=0;j<16;j++){
    float4 v0 = *(const float4*)&rowp[j*16 + s_kb];
    float4 v1 = *(const float4*)&rowp[j*16 + s_kb + 4];
    sum += v0.x+v0.y+v0.z+v0.w + v1.x+v1.y+v1.z+v1.w;
    sq  += v0.x*v0.x+v0.y*v0.y+v0.z*v0.z+v0.w*v0.w
         + v1.x*v1.x+v1.y*v1.y+v1.z*v1.z+v1.w*v1.w;
  }
  sum += __shfl_xor_sync(~0u, sum, 1);
  sq  += __shfl_xor_sync(~0u, sq, 1);
  float mean = sum*(1.f/DMm);
  float rstd = rsqrtf(sq*(1.f/DMm) - mean*mean + 1e-5f);
  __syncthreads();
#define LOADA(k0_) { int kk_=(k0_)+s_kb;                                           \
    raA0 = *(const float4*)&rowp[kk_];                                             \
    raA1 = *(const float4*)&rowp[kk_+4];                                           \
    raA0.x=(raA0.x-mean)*rstd*sG[kk_+0]+sBt[kk_+0];                                \
    raA0.y=(raA0.y-mean)*rstd*sG[kk_+1]+sBt[kk_+1];                                \
    raA0.z=(raA0.z-mean)*rstd*sG[kk_+2]+sBt[kk_+2];                                \
    raA0.w=(raA0.w-mean)*rstd*sG[kk_+3]+sBt[kk_+3];                                \
    raA1.x=(raA1.x-mean)*rstd*sG[kk_+4]+sBt[kk_+4];                                \
    raA1.y=(raA1.y-mean)*rstd*sG[kk_+5]+sBt[kk_+5];                                \
    raA1.z=(raA1.z-mean)*rstd*sG[kk_+6]+sBt[kk_+6];                                \
    raA1.w=(raA1.w-mean)*rstd*sG[kk_+7]+sBt[kk_+7]; }
#define LOADB(k0_) { int kb_ = (k0_) + s_bq*4;                                     \
                     rb0 = W[(size_t)(kb_+0)*(2*DIi) + col0 + s_bn];               \
                     rb1 = W[(size_t)(kb_+1)*(2*DIi) + col0 + s_bn];               \
                     rb2 = W[(size_t)(kb_+2)*(2*DIi) + col0 + s_bn];               \
                     rb3 = W[(size_t)(kb_+3)*(2*DIi) + col0 + s_bn]; }
  TC_BODY(DMm);
#undef LOADA
#undef LOADB
  __half* dst = (col0 < DIi) ? g_xs : g_z;
  int cb = (col0 < DIi) ? col0 : col0 - DIi;
  #pragma unroll
  for (int mt=0;mt<2;mt++)
    #pragma unroll
    for (int nt=0;nt<4;nt++){
      int r = row0 + wm*32 + mt*16 + (lane>>2);
      int c = cb + wn*32 + nt*8 + (lane&3)*2;
      *(unsigned*)&dst[(size_t)r*DIi + c]     = h2pack(acc[mt][nt][0], acc[mt][nt][1]);
      *(unsigned*)&dst[(size_t)(r+8)*DIi + c] = h2pack(acc[mt][nt][2], acc[mt][nt][3]);
    }
}

// x-proj split-K: xc[8192,512](half) @ [xd(32)|xB(16)|xC(16)] -> projp[kz] (fp32)
__global__ void k_gemm_x(const float* __restrict__ xdw0, const float* __restrict__ xbw0,
                         const float* __restrict__ xcw0,
                         const float* __restrict__ xdw1, const float* __restrict__ xbw1,
                         const float* __restrict__ xcw1){
  int kz = blockIdx.x, row0 = blockIdx.y*128;
  int half = row0 >> 12;
  int kbase = kz*(DIi/KS);
  TC_DECL();
  const float* bsrc; int ldb, boff;
  if      (s_bn < 32){ bsrc = half?xdw1:xdw0; ldb = 32; boff = s_bn;      }
  else if (s_bn < 48){ bsrc = half?xbw1:xbw0; ldb = 16; boff = s_bn - 32; }
  else               { bsrc = half?xcw1:xcw0; ldb = 16; boff = s_bn - 48; }
#define LOADA(k0_) { raH = *(const uint4*)&g_xc[(size_t)(row0+s_r)*DIi + kbase+(k0_)+s_kb]; }
#define LOADB(k0_) { int kb_ = kbase + (k0_) + s_bq*4;                                   \
                     rb0 = bsrc[(kb_+0)*ldb + boff];                                     \
                     rb1 = bsrc[(kb_+1)*ldb + boff];                                     \
                     rb2 = bsrc[(kb_+2)*ldb + boff];                                     \
                     rb3 = bsrc[(kb_+3)*ldb + boff]; }
  TC_BODY_H(DIi/KS);
#undef LOADA
#undef LOADB
  float* dst = g_projp + (size_t)kz*M2*64;
  #pragma unroll
  for (int mt=0;mt<2;mt++)
    #pragma unroll
    for (int nt=0;nt<4;nt++){
      int r = row0 + wm*32 + mt*16 + (lane>>2);
      int c = wn*32 + nt*8 + (lane&3)*2;
      *(float2*)&dst[(size_t)r*64 + c]     = make_float2(acc[mt][nt][0], acc[mt][nt][1]);
      *(float2*)&dst[(size_t)(r+8)*64 + c] = make_float2(acc[mt][nt][2], acc[mt][nt][3]);
    }
}

__global__ void k_xred(){
  int i = blockIdx.x*256 + threadIdx.x;   // M2*16 float4s
  float4 a = reinterpret_cast<const float4*>(g_projp)[i];
  float4 b = reinterpret_cast<const float4*>(g_projp + (size_t)M2*64)[i];
  float4 c = reinterpret_cast<const float4*>(g_projp + (size_t)2*M2*64)[i];
  float4 d = reinterpret_cast<const float4*>(g_projp + (size_t)3*M2*64)[i];
  float4 s = make_float4(a.x+b.x+c.x+d.x, a.y+b.y+c.y+d.y,
                         a.z+b.z+c.z+d.z, a.w+b.w+c.w+d.w);
  reinterpret_cast<float4*>(g_proj)[i] = s;
  h4store(&g_projh[i*4], s);
}

// delta: softplus(projh[:, :32] @ dtp_w[32,512] + dtp_b) -> g_delta (half)
__global__ void k_gemm_dt(const float* __restrict__ Wd0, const float* __restrict__ bd0,
                          const float* __restrict__ Wd1, const float* __restrict__ bd1){
  int col0 = blockIdx.x*64, row0 = blockIdx.y*128;
  int half = row0 >> 12;
  const float* Wd = half ? Wd1 : Wd0;
  const float* bd = half ? bd1 : bd0;
  TC_DECL();
#define LOADA(k0_) { raH = *(const uint4*)&g_projh[(size_t)(row0+s_r)*64 + (k0_)+s_kb]; }
#define LOADB(k0_) { int kb_ = (k0_) + s_bq*4;                                      \
                     rb0 = Wd[(kb_+0)*DIi + col0 + s_bn];                           \
                     rb1 = Wd[(kb_+1)*DIi + col0 + s_bn];                           \
                     rb2 = Wd[(kb_+2)*DIi + col0 + s_bn];                           \
                     rb3 = Wd[(kb_+3)*DIi + col0 + s_bn]; }
  TC_BODY_H(RR);
#undef LOADA
#undef LOADB
  #pragma unroll
  for (int mt=0;mt<2;mt++)
    #pragma unroll
    for (int nt=0;nt<4;nt++){
      int r = row0 + wm*32 + mt*16 + (lane>>2);
      int c = col0 + wn*32 + nt*8 + (lane&3)*2;
      float b0 = bd[c], b1 = bd[c+1];
      *(unsigned*)&g_delta[(size_t)r*DIi + c] =
          h2pack(spf(acc[mt][nt][0]+b0), spf(acc[mt][nt][1]+b1));
      *(unsigned*)&g_delta[(size_t)(r+8)*DIi + c] =
          h2pack(spf(acc[mt][nt][2]+b0), spf(acc[mt][nt][3]+b1));
    }
}

// out_proj: yg[8192,512](half) @ out_w[512,256] + residual (in place on g_res)
__global__ void k_gemm_out(const float* __restrict__ W0, const float* __restrict__ W1){
  int col0 = blockIdx.x*64, row0 = blockIdx.y*128;
  int half = row0 >> 12;
  const float* W = half ? W1 : W0;
  TC_DECL();
#define LOADA(k0_) { raH = *(const uint4*)&g_yg[(size_t)(row0+s_r)*DIi + (k0_)+s_kb]; }
#define LOADB(k0_) { int kb_ = (k0_) + s_bq*4;                                     \
                     rb0 = W[(kb_+0)*DMm + col0 + s_bn];                           \
                     rb1 = W[(kb_+1)*DMm + col0 + s_bn];                           \
                     rb2 = W[(kb_+2)*DMm + col0 + s_bn];                           \
                     rb3 = W[(kb_+3)*DMm + col0 + s_bn]; }
  TC_BODY_H(DIi);
#undef LOADA
#undef LOADB
  #pragma unroll
  for (int mt=0;mt<2;mt++)
    #pragma unroll
    for (int nt=0;nt<4;nt++){
      int r = row0 + wm*32 + mt*16 + (lane>>2);
      int c = col0 + wn*32 + nt*8 + (lane&3)*2;
      float2 o0 = *(const float2*)&g_res[(size_t)r*DMm + c];
      float2 o1 = *(const float2*)&g_res[(size_t)(r+8)*DMm + c];
      *(float2*)&g_res[(size_t)r*DMm + c] =
          make_float2(acc[mt][nt][0]+o0.x, acc[mt][nt][1]+o0.y);
      *(float2*)&g_res[(size_t)(r+8)*DMm + c] =
          make_float2(acc[mt][nt][2]+o1.x, acc[mt][nt][3]+o1.y);
    }
}

// merge: concat(res_half0, res_half1_reversed)[4096,512] @ merge_w[512,256] -> out
__global__ void k_merge(const float* __restrict__ W, float* __restrict__ out){
  int col0 = blockIdx.x*64, row0 = blockIdx.y*128;
  TC_DECL();
  int r_ = row0 + s_r;
  int b_ = r_ >> 11, s_ = r_ & (Ss-1);
  int rrev = MM + b_*Ss + (Ss-1-s_);
#define LOADA(k0_) {                                                               \
    int kk0 = (k0_)+s_kb, kk1 = (k0_)+s_kb+4;                                      \
    raA0 = *(const float4*)((kk0 < DMm) ? (g_res + (size_t)r_*DMm + kk0)           \
                                        : (g_res + (size_t)rrev*DMm + kk0-DMm));   \
    raA1 = *(const float4*)((kk1 < DMm) ? (g_res + (size_t)r_*DMm + kk1)           \
                                        : (g_res + (size_t)rrev*DMm + kk1-DMm)); }
#define LOADB(k0_) { int kb_ = (k0_) + s_bq*4;                                     \
                     rb0 = W[(kb_+0)*DMm + col0 + s_bn];                           \
                     rb1 = W[(kb_+1)*DMm + col0 + s_bn];                           \
                     rb2 = W[(kb_+2)*DMm + col0 + s_bn];                           \
                     rb3 = W[(kb_+3)*DMm + col0 + s_bn]; }
  TC_BODY(2*DMm);
#undef LOADA
#undef LOADB
  #pragma unroll
  for (int mt=0;mt<2;mt++)
    #pragma unroll
    for (int nt=0;nt<4;nt++){
      int r = row0 + wm*32 + mt*16 + (lane>>2);
      int c = col0 + wn*32 + nt*8 + (lane&3)*2;
      *(float2*)&out[(size_t)r*DMm + c]     = make_float2(acc[mt][nt][0], acc[mt][nt][1]);
      *(float2*)&out[(size_t)(r+8)*DMm + c] = make_float2(acc[mt][nt][2], acc[mt][nt][3]);
    }
}

// ---------------- causal depthwise conv (K=4) + silu, half I/O ----------------
__global__ void k_conv(const float* __restrict__ cw0, const float* __restrict__ cb0,
                       const float* __restrict__ cw1, const float* __restrict__ cb1){
  int idx = blockIdx.x*256 + threadIdx.x;   // (M2/4)*128
  int d4 = idx & 127, g = idx >> 7;         // g in [0, M2/4)
  int b2 = g >> 9, sg = g & 511;            // seq 0..3, group within seq
  int half = b2 >> 1;
  const float* cw = half ? cw1 : cw0;
  const float* cb = half ? cb1 : cb0;
  int m0 = b2*Ss + sg*4;
  int d = d4*4;
  float4 w0 = *(const float4*)(cw + (d+0)*4);
  float4 w1 = *(const float4*)(cw + (d+1)*4);
  float4 w2 = *(const float4*)(cw + (d+2)*4);
  float4 w3 = *(const float4*)(cw + (d+3)*4);
  float4 bv = *(const float4*)(cb + d);
  float4 x0, x1, x2;
  if (sg > 0){
    x0 = h4load(&g_xs[(size_t)(m0-3)*DIi + d]);
    x1 = h4load(&g_xs[(size_t)(m0-2)*DIi + d]);
    x2 = h4load(&g_xs[(size_t)(m0-1)*DIi + d]);
  } else {
    x0 = x1 = x2 = make_float4(0.f,0.f,0.f,0.f);
  }
  #pragma unroll
  for (int s=0;s<4;s++){
    float4 x3 = h4load(&g_xs[(size_t)(m0+s)*DIi + d]);
    float4 a;
    a.x = bv.x + w0.x*x0.x + w0.y*x1.x + w0.z*x2.x + w0.w*x3.x;
    a.y = bv.y + w1.x*x0.y + w1.y*x1.y + w1.z*x2.y + w1.w*x3.y;
    a.z = bv.z + w2.x*x0.z + w2.y*x1.z + w2.z*x2.z + w2.w*x3.z;
    a.w = bv.w + w3.x*x0.w + w3.y*x1.w + w3.z*x2.w + w3.w*x3.w;
    a.x = siluf(a.x); a.y = siluf(a.y); a.z = siluf(a.z); a.w = siluf(a.w);
    h4store(&g_xc[(size_t)(m0+s)*DIi + d], a);
    x0 = x1; x1 = x2; x2 = x3;
  }
}

// dA helper: if A[n] == -(n+1) (the actual dataset), dA_n = r^(n+1) with
// r = exp(-delta): 1 MUFU + 15 FMUL instead of 16 MUFU.
__device__ __forceinline__ void dA_compute(float* dAv, const float* A,
                                           float dlt, bool fast){
  if (fast){
    float r = __expf(-dlt);
    dAv[0] = r; dAv[1] = r*r;
    #pragma unroll
    for (int n=2;n<NN;n++) dAv[n] = dAv[n>>1]*dAv[(n-1)>>1];
  } else {
    #pragma unroll
    for (int n=0;n<NN;n++) dAv[n] = __expf(dlt*A[n]);
  }
}

__device__ __forceinline__ bool a_fast(const float* A){
  bool f = true;
  #pragma unroll
  for (int n=0;n<NN;n++) f = f && (fabsf(A[n] + (float)(n+1)) < 1e-5f*(n+1));
  return f;
}

// ---------------- chunked scan phase 1 ----------------
__global__ void k_scan1(const float* __restrict__ Alog0, const float* __restrict__ Alog1){
  __shared__ float sB[CHUNK][NN];
  int blk = blockIdx.x;               // 2 * NSEQ*NCH = 512
  int bc_ = blk >> 1;                 // 0..255
  int seq = bc_ >> 6, c = bc_ & 63;
  int half = seq >> 1;
  const float* Alog = half ? Alog1 : Alog0;
  int d = (blk & 1)*256 + threadIdx.x;
  int m0 = seq*Ss + c*CHUNK;
  { int i0 = threadIdx.x, i1 = threadIdx.x + 256;
    sB[i0>>4][i0&15] = g_proj[(size_t)(m0+(i0>>4))*64 + 32 + (i0&15)];
    sB[i1>>4][i1&15] = g_proj[(size_t)(m0+(i1>>4))*64 + 32 + (i1&15)]; }
  float A[NN];
  #pragma unroll
  for (int n=0;n<NN;n++) A[n] = -__expf(Alog[d*NN + n]);
  bool fast = a_fast(A);
  __syncthreads();
  float h[NN];
  #pragma unroll
  for (int n=0;n<NN;n++) h[n] = 0.f;
  float sd = 0.f;
  #pragma unroll 1
  for (int s=0;s<CHUNK;s++){
    size_t m = m0 + s;
    float dlt = __half2float(g_delta[m*DIi + d]);
    float dx  = dlt * __half2float(g_xc[m*DIi + d]);
    sd += dlt;
    float dAv[NN];
    dA_compute(dAv, A, dlt, fast);
    #pragma unroll
    for (int n=0;n<NN;n++) h[n] = dAv[n]*h[n] + dx*sB[s][n];
  }
  size_t base = ((size_t)bc_*DIi + d)*NN;
  float Pv[NN];
  dA_compute(Pv, A, sd, fast);
  #pragma unroll
  for (int n=0;n<NN;n++){ g_Q[base+n]=h[n]; g_P[base+n]=Pv[n]; }
}

// ---------------- phase 2: combine across chunks ----------------
__global__ void k_comb(){
  int i = blockIdx.x*128 + threadIdx.x;     // NSEQ*DIi*NN = 32768
  int n = i & 15, d = (i >> 4) & (DIi-1), seq = i >> 13;
  float H = 0.f;
  for (int c=0;c<NCH;c++){
    size_t idx = (((size_t)(seq*NCH+c))*DIi + d)*NN + n;
    g_Hin[idx] = H;
    H = g_P[idx]*H + g_Q[idx];
  }
}

// ---------------- phase 3: replay + gated output ----------------
__global__ void k_scan2(const float* __restrict__ Alog0, const float* __restrict__ Alog1,
                        const float* __restrict__ Dp0, const float* __restrict__ Dp1){
  __shared__ float sB[CHUNK][NN];
  __shared__ float sC[CHUNK][NN];
  int blk = blockIdx.x;
  int bc_ = blk >> 1;
  int seq = bc_ >> 6, c = bc_ & 63;
  int half = seq >> 1;
  const float* Alog = half ? Alog1 : Alog0;
  const float* Dp   = half ? Dp1   : Dp0;
  int d = (blk & 1)*256 + threadIdx.x;
  int m0 = seq*Ss + c*CHUNK;
  { int i0 = threadIdx.x, i1 = threadIdx.x + 256;
    sB[i0>>4][i0&15] = g_proj[(size_t)(m0+(i0>>4))*64 + 32 + (i0&15)];
    sB[i1>>4][i1&15] = g_proj[(size_t)(m0+(i1>>4))*64 + 32 + (i1&15)];
    sC[i0>>4][i0&15] = g_proj[(size_t)(m0+(i0>>4))*64 + 48 + (i0&15)];
    sC[i1>>4][i1&15] = g_proj[(size_t)(m0+(i1>>4))*64 + 48 + (i1&15)]; }
  float A[NN];
  #pragma unroll
  for (int n=0;n<NN;n++) A[n] = -__expf(Alog[d*NN + n]);
  bool fast = a_fast(A);
  float h[NN];
  size_t base = ((size_t)bc_*DIi + d)*NN;
  #pragma unroll
  for (int n=0;n<NN;n++) h[n] = g_Hin[base+n];
  float Dv = Dp[d];
  __syncthreads();
  #pragma unroll 1
  for (int s=0;s<CHUNK;s++){
    size_t m = m0 + s;
    float dlt = __half2float(g_delta[m*DIi + d]);
    float x   = __half2float(g_xc[m*DIi + d]);
    float dx  = dlt * x;
    float dAv[NN];
    dA_compute(dAv, A, dlt, fast);
    float y = 0.f;
    #pragma unroll
    for (int n=0;n<NN;n++){
      h[n] = dAv[n]*h[n] + dx*sB[s][n];
      y += h[n]*sC[s][n];
    }
    y += Dv*x;
    float zv = __half2float(g_z[m*DIi + d]);
    g_yg[m*DIi + d] = __float2half(y * siluf(zv));
  }
}

// ---------------- driver ----------------
extern "C" void kernel_launch(void* const* d_in, const int* in_sizes, int n_in,
                              void* d_out, int out_size){
  const float* x      = (const float*)d_in[0];
  const float* in_w   = (const float*)d_in[1];
  const float* conv_w = (const float*)d_in[2];
  const float* conv_b = (const float*)d_in[3];
  const float* A_log  = (const float*)d_in[4];
  const float* xd_w   = (const float*)d_in[5];
  const float* xB_w   = (const float*)d_in[6];
  const float* xC_w   = (const float*)d_in[7];
  const float* dtp_w  = (const float*)d_in[8];
  const float* dtp_b  = (const float*)d_in[9];
  const float* Dp     = (const float*)d_in[10];
  const float* out_w  = (const float*)d_in[11];
  const float* ln_g   = (const float*)d_in[12];
  const float* ln_b   = (const float*)d_in[13];
  const float* merge_w= (const float*)d_in[14];
  float* out = (float*)d_out;

  k_init<<<M2*64/256, 256>>>(x);
  for (int bi=0; bi<2; bi++){
    int b0 = bi, b1 = 2 + bi;
    k_gemm_in <<<dim3(16,64), 256>>>(in_w + (size_t)b0*DMm*2*DIi,
                                     in_w + (size_t)b1*DMm*2*DIi,
                                     ln_g + b0*DMm, ln_b + b0*DMm,
                                     ln_g + b1*DMm, ln_b + b1*DMm);
    k_conv    <<<(M2/4)*128/256, 256>>>(conv_w + b0*DIi*4, conv_b + b0*DIi,
                                        conv_w + b1*DIi*4, conv_b + b1*DIi);
    k_gemm_x  <<<dim3(KS,64), 256>>>(xd_w + b0*DIi*RR, xB_w + b0*DIi*NN, xC_w + b0*DIi*NN,
                                     xd_w + b1*DIi*RR, xB_w + b1*DIi*NN, xC_w + b1*DIi*NN);
    k_xred    <<<M2*16/256, 256>>>();
    k_gemm_dt <<<dim3(8,64), 256>>>(dtp_w + b0*RR*DIi, dtp_b + b0*DIi,
                                    dtp_w + b1*RR*DIi, dtp_b + b1*DIi);
    k_scan1   <<<2*NSEQ*NCH, 256>>>(A_log + b0*DIi*NN, A_log + b1*DIi*NN);
    k_comb    <<<256, 128>>>();
    k_scan2   <<<2*NSEQ*NCH, 256>>>(A_log + b0*DIi*NN, A_log + b1*DIi*NN,
                                    Dp + b0*DIi, Dp + b1*DIi);
    k_gemm_out<<<dim3(4,64), 256>>>(out_w + (size_t)b0*DIi*DMm,
                                    out_w + (size_t)b1*DIi*DMm);
  }
  k_merge<<<dim3(4,32), 256>>>(merge_w, out);
}